// round 1
// baseline (speedup 1.0000x reference)
#include <cuda_runtime.h>
#include <math.h>
#include <stdint.h>

// ---------------- problem constants ----------------
#define BATCH   4
#define TSEQ    288
#define TVIS    256
#define TQRY    32
#define DMODEL  1024
#define DINNER  2048
#define NHEADS  32
#define NSTATE  128
#define PDIM    64          // DINNER / NHEADS
#define NLAYERS 12
#define PROJ_DIM 4384       // 2*DINNER + 2*NSTATE + NHEADS
#define EDIM    1536
#define ROWS    (BATCH*TSEQ)    // 1152
#define ALPHA_C 0.5f

// ---------------- scratch (device globals; no allocation) ----------------
__device__ float g_hidden[ROWS*DMODEL];
__device__ float g_xin   [ROWS*DMODEL];
__device__ float g_proj  [ROWS*PROJ_DIM];
__device__ float g_yraw  [ROWS*DINNER];
__device__ float g_yg    [ROWS*DINNER];
__device__ float g_pooled[BATCH*DMODEL];

// ---------------- helpers ----------------
__device__ __forceinline__ float block_reduce_sum_256(float v, float* red)
{
    // blockDim.x == 256
    #pragma unroll
    for (int o = 16; o; o >>= 1) v += __shfl_xor_sync(0xffffffffu, v, o);
    const int warp = threadIdx.x >> 5, lane = threadIdx.x & 31;
    if (lane == 0) red[warp] = v;
    __syncthreads();
    if (threadIdx.x < 32) {
        float t = (threadIdx.x < 8) ? red[threadIdx.x] : 0.f;
        #pragma unroll
        for (int o = 4; o; o >>= 1) t += __shfl_xor_sync(0xffffffffu, t, o);
        if (threadIdx.x == 0) red[0] = t;
    }
    __syncthreads();
    return red[0];
}

// ---------------- SGEMM: C[map(r)] (+)= A[r]@B + bias ----------------
// A: MxK row-major, B: KxN row-major, C row stride = N.
// Output row remap: orow = (r / Tin) * Tout + toff + (r % Tin).
// Requires: M % 128 == 0, K % 8 == 0. N guarded.
__global__ void sgemm_k(const float* __restrict__ A, const float* __restrict__ Bm,
                        float* __restrict__ C, int M, int N, int K,
                        const float* __restrict__ bias, int accum,
                        int Tin, int Tout, int toff)
{
    __shared__ float As[8][128];
    __shared__ float Bs[8][128];
    const int tid  = threadIdx.x;          // 256 threads
    const int row0 = blockIdx.y * 128;
    const int col0 = blockIdx.x * 128;
    const int tr   = (tid / 16) * 8;
    const int tc   = (tid % 16) * 8;
    const int a_r  = tid >> 1;
    const int a_c  = (tid & 1) * 4;
    const int b_r  = tid >> 5;
    const int b_c  = (tid & 31) * 4;

    float acc[8][8];
    #pragma unroll
    for (int i = 0; i < 8; i++)
        #pragma unroll
        for (int j = 0; j < 8; j++) acc[i][j] = 0.f;

    for (int k0 = 0; k0 < K; k0 += 8) {
        float4 av = *reinterpret_cast<const float4*>(A + (size_t)(row0 + a_r)*K + k0 + a_c);
        As[a_c+0][a_r] = av.x; As[a_c+1][a_r] = av.y;
        As[a_c+2][a_r] = av.z; As[a_c+3][a_r] = av.w;

        const int bc = col0 + b_c;
        float4 bv;
        if (bc + 3 < N) {
            bv = *reinterpret_cast<const float4*>(Bm + (size_t)(k0 + b_r)*N + bc);
        } else {
            bv.x = (bc + 0 < N) ? Bm[(size_t)(k0 + b_r)*N + bc + 0] : 0.f;
            bv.y = (bc + 1 < N) ? Bm[(size_t)(k0 + b_r)*N + bc + 1] : 0.f;
            bv.z = (bc + 2 < N) ? Bm[(size_t)(k0 + b_r)*N + bc + 2] : 0.f;
            bv.w = 0.f;
        }
        *reinterpret_cast<float4*>(&Bs[b_r][b_c]) = bv;
        __syncthreads();

        #pragma unroll
        for (int kk = 0; kk < 8; kk++) {
            float ar[8], br[8];
            #pragma unroll
            for (int i = 0; i < 8; i++) ar[i] = As[kk][tr + i];
            #pragma unroll
            for (int j = 0; j < 8; j++) br[j] = Bs[kk][tc + j];
            #pragma unroll
            for (int i = 0; i < 8; i++)
                #pragma unroll
                for (int j = 0; j < 8; j++)
                    acc[i][j] = fmaf(ar[i], br[j], acc[i][j]);
        }
        __syncthreads();
    }

    #pragma unroll
    for (int i = 0; i < 8; i++) {
        const int r    = row0 + tr + i;
        const int orow = (r / Tin) * Tout + toff + (r % Tin);
        #pragma unroll
        for (int j = 0; j < 8; j++) {
            const int c = col0 + tc + j;
            if (c < N) {
                float v = acc[i][j];
                if (bias)  v += bias[c];
                const size_t idx = (size_t)orow * N + c;
                if (accum) v += C[idx];
                C[idx] = v;
            }
        }
    }
}

// ---------------- RMSNorm over last dim ----------------
__global__ void rmsnorm_k(const float* __restrict__ x, const float* __restrict__ w,
                          float* __restrict__ out, int D)
{
    __shared__ float red[32];
    const int r = blockIdx.x;
    const float* xr = x + (size_t)r * D;
    float s = 0.f;
    for (int d = threadIdx.x; d < D; d += 256) { float v = xr[d]; s = fmaf(v, v, s); }
    const float tot = block_reduce_sum_256(s, red);
    const float rms = rsqrtf(tot / (float)D + 1e-5f);
    for (int d = threadIdx.x; d < D; d += 256)
        out[(size_t)r * D + d] = xr[d] * rms * w[d];
}

// ---------------- SSD sequential scan ----------------
// One block per (b, h). 8 warps: warp w owns p in [w*8, w*8+8); lane owns n in [lane*4, lane*4+4).
// State h[p][n] lives in registers (32 floats / thread). 288 sequential steps.
__global__ void scan_k(const float* __restrict__ proj,
                       const float* __restrict__ dt_bias,
                       const float* __restrict__ A_log,
                       const float* __restrict__ Dssm,
                       float* __restrict__ yraw)
{
    const int b    = blockIdx.x >> 5;
    const int h    = blockIdx.x & 31;
    const int tid  = threadIdx.x;
    const int warp = tid >> 5, lane = tid & 31;

    __shared__ float sx[PDIM];
    __shared__ float sB[NSTATE];
    __shared__ float sC[NSTATE];
    __shared__ float s_dt;

    const float dtb  = dt_bias[h];
    const float Aval = -expf(A_log[h]);
    const float Dval = Dssm[h];

    float hs[8][4];
    #pragma unroll
    for (int i = 0; i < 8; i++)
        #pragma unroll
        for (int j = 0; j < 4; j++) hs[i][j] = 0.f;

    float xprev[8];
    float bprev[4];
    float dtprev = 0.f;
    #pragma unroll
    for (int i = 0; i < 8; i++) xprev[i] = 0.f;
    #pragma unroll
    for (int j = 0; j < 4; j++) bprev[j] = 0.f;

    const int pbase = warp * 8;
    const int nbase = lane * 4;

    for (int t = 0; t < TSEQ; t++) {
        const int row = b * TSEQ + t;
        const float* pr = proj + (size_t)row * PROJ_DIM;

        if (tid < PDIM)                    sx[tid]                 = pr[DINNER + h*PDIM + tid];
        else if (tid < PDIM + NSTATE)      sB[tid - PDIM]          = pr[2*DINNER + (tid - PDIM)];
        else                               sC[tid - PDIM - NSTATE] = pr[2*DINNER + NSTATE + (tid - PDIM - NSTATE)];
        if (tid < PDIM)                    sC[(NSTATE - PDIM) + tid] = pr[2*DINNER + NSTATE + (NSTATE - PDIM) + tid];
        if (tid == 0) {
            float v = pr[2*DINNER + 2*NSTATE + h] + dtb;
            s_dt = (v > 20.f) ? v : log1pf(expf(v));   // softplus
        }
        __syncthreads();

        const float dt  = s_dt;
        const float da  = expf(dt * Aval);
        const float cu  = (1.f - ALPHA_C) * dt;
        const float cup = da * ALPHA_C * dtprev;

        float bc[4], cc[4];
        #pragma unroll
        for (int j = 0; j < 4; j++) { bc[j] = sB[nbase + j]; cc[j] = sC[nbase + j]; }

        #pragma unroll
        for (int i = 0; i < 8; i++) {
            const float xr  = sx[pbase + i];
            const float xpi = cup * xprev[i];
            const float xci = cu  * xr;
            float yp = 0.f;
            #pragma unroll
            for (int j = 0; j < 4; j++) {
                const float u = fmaf(xpi, bprev[j], xci * bc[j]);
                hs[i][j] = fmaf(da, hs[i][j], u);
                yp = fmaf(hs[i][j], cc[j], yp);
            }
            #pragma unroll
            for (int o = 16; o; o >>= 1) yp += __shfl_xor_sync(0xffffffffu, yp, o);
            if (lane == 0)
                yraw[(size_t)row * DINNER + h*PDIM + pbase + i] = fmaf(Dval, xr, yp);
            xprev[i] = xr;
        }
        #pragma unroll
        for (int j = 0; j < 4; j++) bprev[j] = bc[j];
        dtprev = dt;
        __syncthreads();
    }
}

// ---------------- y * silu(z), then rmsnorm(gnorm_w) over DINNER ----------------
__global__ void gate_gnorm_k(const float* __restrict__ proj,
                             const float* __restrict__ yraw,
                             const float* __restrict__ gw,
                             float* __restrict__ yg)
{
    __shared__ float red[32];
    const int r = blockIdx.x;
    const float* pz = proj + (size_t)r * PROJ_DIM;   // z: first DINNER cols
    const float* yr = yraw + (size_t)r * DINNER;
    float* og = yg + (size_t)r * DINNER;

    float s = 0.f;
    for (int d = threadIdx.x; d < DINNER; d += 256) {
        const float z   = pz[d];
        const float sig = 1.f / (1.f + expf(-z));
        const float g   = yr[d] * z * sig;
        og[d] = g;
        s = fmaf(g, g, s);
    }
    const float tot = block_reduce_sum_256(s, red);
    const float rms = rsqrtf(tot / (float)DINNER + 1e-5f);
    for (int d = threadIdx.x; d < DINNER; d += 256)
        og[d] = og[d] * rms * gw[d];
}

// ---------------- mean over T per batch ----------------
__global__ void pool_k(const float* __restrict__ xin, float* __restrict__ pooled)
{
    const int b = blockIdx.x;
    for (int d = threadIdx.x; d < DMODEL; d += 256) {
        float s = 0.f;
        for (int t = 0; t < TSEQ; t++)
            s += xin[(size_t)(b*TSEQ + t) * DMODEL + d];
        pooled[b*DMODEL + d] = s * (1.f / (float)TSEQ);
    }
}

// ---------------- head GEMM (4x1024 @ 1024x1536) + bias + L2-normalize ----------------
__global__ void head_k(const float* __restrict__ pooled,
                       const float* __restrict__ hw,
                       const float* __restrict__ hb,
                       float* __restrict__ out)
{
    __shared__ float sp[DMODEL];
    __shared__ float so[EDIM];
    __shared__ float red[32];
    const int b = blockIdx.x;

    for (int d = threadIdx.x; d < DMODEL; d += 256) sp[d] = pooled[b*DMODEL + d];
    __syncthreads();

    float acc[EDIM/256];   // 6
    #pragma unroll
    for (int m = 0; m < EDIM/256; m++) acc[m] = hb[threadIdx.x + m*256];
    for (int k = 0; k < DMODEL; k++) {
        const float p = sp[k];
        #pragma unroll
        for (int m = 0; m < EDIM/256; m++)
            acc[m] = fmaf(p, hw[(size_t)k*EDIM + threadIdx.x + m*256], acc[m]);
    }
    #pragma unroll
    for (int m = 0; m < EDIM/256; m++) so[threadIdx.x + m*256] = acc[m];
    __syncthreads();

    float s = 0.f;
    for (int e = threadIdx.x; e < EDIM; e += 256) s = fmaf(so[e], so[e], s);
    const float tot = block_reduce_sum_256(s, red);
    const float inv = 1.f / fmaxf(sqrtf(tot), 1e-12f);
    for (int e = threadIdx.x; e < EDIM; e += 256)
        out[(size_t)b*EDIM + e] = so[e] * inv;
}

// ---------------- host launcher ----------------
extern "C" void kernel_launch(void* const* d_in, const int* in_sizes, int n_in,
                              void* d_out, int out_size)
{
    const float* visual   = (const float*)d_in[0];
    const float* query    = (const float*)d_in[1];
    const float* vis_w    = (const float*)d_in[2];
    const float* vis_b    = (const float*)d_in[3];
    const float* qry_w    = (const float*)d_in[4];
    const float* qry_b    = (const float*)d_in[5];
    const float* norm_ws  = (const float*)d_in[6];
    const float* in_ws    = (const float*)d_in[7];
    const float* dt_bias  = (const float*)d_in[8];
    const float* A_logs   = (const float*)d_in[9];
    const float* D_ssm    = (const float*)d_in[10];
    const float* gnorm_ws = (const float*)d_in[11];
    const float* out_ws   = (const float*)d_in[12];
    const float* norm_f_w = (const float*)d_in[13];
    const float* head_w   = (const float*)d_in[14];
    const float* head_b   = (const float*)d_in[15];
    float* out = (float*)d_out;

    float *hidden, *xin, *proj, *yraw, *yg, *pooled;
    cudaGetSymbolAddress((void**)&hidden, g_hidden);
    cudaGetSymbolAddress((void**)&xin,    g_xin);
    cudaGetSymbolAddress((void**)&proj,   g_proj);
    cudaGetSymbolAddress((void**)&yraw,   g_yraw);
    cudaGetSymbolAddress((void**)&yg,     g_yg);
    cudaGetSymbolAddress((void**)&pooled, g_pooled);

    const dim3 blk(256);

    // initial projections into hidden[b, t, :] (row remap per batch)
    sgemm_k<<<dim3(DMODEL/128, (BATCH*TVIS)/128), blk>>>(
        visual, vis_w, hidden, BATCH*TVIS, DMODEL, DMODEL, vis_b, 0, TVIS, TSEQ, 0);
    sgemm_k<<<dim3(DMODEL/128, (BATCH*TQRY)/128), blk>>>(
        query, qry_w, hidden, BATCH*TQRY, DMODEL, DMODEL, qry_b, 0, TQRY, TSEQ, TVIS);

    for (int i = 0; i < NLAYERS; i++) {
        rmsnorm_k<<<ROWS, blk>>>(hidden, norm_ws + (size_t)i*DMODEL, xin, DMODEL);

        sgemm_k<<<dim3((PROJ_DIM + 127)/128, ROWS/128), blk>>>(
            xin, in_ws + (size_t)i*DMODEL*PROJ_DIM, proj,
            ROWS, PROJ_DIM, DMODEL, nullptr, 0, ROWS, ROWS, 0);

        scan_k<<<BATCH*NHEADS, blk>>>(
            proj, dt_bias + (size_t)i*NHEADS, A_logs + (size_t)i*NHEADS,
            D_ssm + (size_t)i*NHEADS, yraw);

        gate_gnorm_k<<<ROWS, blk>>>(proj, yraw, gnorm_ws + (size_t)i*DINNER, yg);

        sgemm_k<<<dim3(DMODEL/128, ROWS/128), blk>>>(
            yg, out_ws + (size_t)i*DINNER*DMODEL, hidden,
            ROWS, DMODEL, DINNER, nullptr, 1, ROWS, ROWS, 0);
    }

    rmsnorm_k<<<ROWS, blk>>>(hidden, norm_f_w, xin, DMODEL);
    pool_k<<<BATCH, blk>>>(xin, pooled);
    head_k<<<BATCH, blk>>>(pooled, head_w, head_b, out);
}

// round 2
// speedup vs baseline: 1.4676x; 1.4676x over previous
#include <cuda_runtime.h>
#include <math.h>
#include <stdint.h>

// ---------------- problem constants ----------------
#define BATCH   4
#define TSEQ    288
#define TVIS    256
#define TQRY    32
#define DMODEL  1024
#define DINNER  2048
#define NHEADS  32
#define NSTATE  128
#define PDIM    64          // DINNER / NHEADS
#define NLAYERS 12
#define PROJ_DIM 4384       // 2*DINNER + 2*NSTATE + NHEADS
#define EDIM    1536
#define ROWS    (BATCH*TSEQ)    // 1152
#define ALPHA_C 0.5f

// ---------------- scratch (device globals; no allocation) ----------------
__device__ float g_hidden[ROWS*DMODEL];
__device__ float g_xin   [ROWS*DMODEL];
__device__ float g_proj  [ROWS*PROJ_DIM];
__device__ float g_yraw  [ROWS*DINNER];
__device__ float g_yg    [ROWS*DINNER];
__device__ float g_pooled[BATCH*DMODEL];

// ---------------- helpers ----------------
__device__ __forceinline__ float block_reduce_sum_256(float v, float* red)
{
    #pragma unroll
    for (int o = 16; o; o >>= 1) v += __shfl_xor_sync(0xffffffffu, v, o);
    const int warp = threadIdx.x >> 5, lane = threadIdx.x & 31;
    if (lane == 0) red[warp] = v;
    __syncthreads();
    if (threadIdx.x < 32) {
        float t = (threadIdx.x < 8) ? red[threadIdx.x] : 0.f;
        #pragma unroll
        for (int o = 4; o; o >>= 1) t += __shfl_xor_sync(0xffffffffu, t, o);
        if (threadIdx.x == 0) red[0] = t;
    }
    __syncthreads();
    return red[0];
}

// 3xTF32 split: x = hi + lo, both representable as tf32 (rounded).
__device__ __forceinline__ void tf32_split(float x, float& hi, float& lo)
{
    uint32_t hb; asm("cvt.rna.tf32.f32 %0, %1;" : "=r"(hb) : "f"(x));
    hi = __uint_as_float(hb);
    float r = x - hi;
    uint32_t lb; asm("cvt.rna.tf32.f32 %0, %1;" : "=r"(lb) : "f"(r));
    lo = __uint_as_float(lb);
}

#define MMA_TF32(cc, aa, bb)                                                     \
  asm volatile("mma.sync.aligned.m16n8k8.row.col.f32.tf32.tf32.f32 "            \
    "{%0,%1,%2,%3}, {%4,%5,%6,%7}, {%8,%9}, {%0,%1,%2,%3};\n"                    \
    : "+f"(cc[0]), "+f"(cc[1]), "+f"(cc[2]), "+f"(cc[3])                         \
    : "r"(aa[0]), "r"(aa[1]), "r"(aa[2]), "r"(aa[3]), "r"(bb[0]), "r"(bb[1]))

// ---------------- tensor-core GEMM (3xTF32, fp32-accurate) ----------------
// C[map(r)] (+)= A[r] @ B + bias.  A: MxK rm, B: KxN rm.
// M % 128 == 0, K % 16 == 0, N guarded.
// Output row remap: orow = (r / Tin) * Tout + toff + (r % Tin).
#define A_STRIDE 20
#define B_STRIDE 136
__global__ __launch_bounds__(256, 1)
void tgemm_k(const float* __restrict__ A, const float* __restrict__ Bm,
             float* __restrict__ C, int M, int N, int K,
             const float* __restrict__ bias, int accum,
             int Tin, int Tout, int toff)
{
    __shared__ float As[2][128][A_STRIDE];   // [hi/lo][m][k(16)]
    __shared__ float Bs[2][16][B_STRIDE];    // [hi/lo][k][n(128)]

    const int tid  = threadIdx.x;
    const int warp = tid >> 5, lane = tid & 31;
    const int gid  = lane >> 2, tg = lane & 3;
    const int row0 = blockIdx.y * 128;
    const int col0 = blockIdx.x * 128;
    const int m_off = (warp & 1) * 64;
    const int n_off = (warp >> 1) * 32;

    float c[4][4][4];
    #pragma unroll
    for (int mi = 0; mi < 4; mi++)
        #pragma unroll
        for (int ni = 0; ni < 4; ni++)
            #pragma unroll
            for (int q = 0; q < 4; q++) c[mi][ni][q] = 0.f;

    // global load mapping
    const int a_r  = tid >> 2;        // 0..63 (and +64)
    const int a_k4 = (tid & 3) * 4;   // 0,4,8,12
    const int b_k  = tid >> 5;        // 0..7 (and +8)
    const int b_n4 = (tid & 31) * 4;  // 0..124
    const int bcol = col0 + b_n4;

    float4 a_reg[2], b_reg[2];

    // ---- prologue: load tile kt = 0 ----
    {
        #pragma unroll
        for (int i = 0; i < 2; i++)
            a_reg[i] = *reinterpret_cast<const float4*>(A + (size_t)(row0 + a_r + i*64)*K + a_k4);
        #pragma unroll
        for (int i = 0; i < 2; i++) {
            const int kk = b_k + i*8;
            if (bcol + 3 < N) {
                b_reg[i] = *reinterpret_cast<const float4*>(Bm + (size_t)kk*N + bcol);
            } else {
                b_reg[i].x = (bcol+0 < N) ? Bm[(size_t)kk*N + bcol+0] : 0.f;
                b_reg[i].y = (bcol+1 < N) ? Bm[(size_t)kk*N + bcol+1] : 0.f;
                b_reg[i].z = (bcol+2 < N) ? Bm[(size_t)kk*N + bcol+2] : 0.f;
                b_reg[i].w = 0.f;
            }
        }
    }

    const int nk = K / 16;
    for (int kt = 0; kt < nk; kt++) {
        // ---- split + STS ----
        #pragma unroll
        for (int i = 0; i < 2; i++) {
            const int r = a_r + i*64;
            float4 h4, l4;
            tf32_split(a_reg[i].x, h4.x, l4.x);
            tf32_split(a_reg[i].y, h4.y, l4.y);
            tf32_split(a_reg[i].z, h4.z, l4.z);
            tf32_split(a_reg[i].w, h4.w, l4.w);
            *reinterpret_cast<float4*>(&As[0][r][a_k4]) = h4;
            *reinterpret_cast<float4*>(&As[1][r][a_k4]) = l4;
        }
        #pragma unroll
        for (int i = 0; i < 2; i++) {
            const int kk = b_k + i*8;
            float4 h4, l4;
            tf32_split(b_reg[i].x, h4.x, l4.x);
            tf32_split(b_reg[i].y, h4.y, l4.y);
            tf32_split(b_reg[i].z, h4.z, l4.z);
            tf32_split(b_reg[i].w, h4.w, l4.w);
            *reinterpret_cast<float4*>(&Bs[0][kk][b_n4]) = h4;
            *reinterpret_cast<float4*>(&Bs[1][kk][b_n4]) = l4;
        }
        __syncthreads();

        // ---- prefetch next tile into regs (overlaps with MMA below) ----
        if (kt + 1 < nk) {
            const int k0 = (kt + 1) * 16;
            #pragma unroll
            for (int i = 0; i < 2; i++)
                a_reg[i] = *reinterpret_cast<const float4*>(A + (size_t)(row0 + a_r + i*64)*K + k0 + a_k4);
            #pragma unroll
            for (int i = 0; i < 2; i++) {
                const int kk = k0 + b_k + i*8;
                if (bcol + 3 < N) {
                    b_reg[i] = *reinterpret_cast<const float4*>(Bm + (size_t)kk*N + bcol);
                } else {
                    b_reg[i].x = (bcol+0 < N) ? Bm[(size_t)kk*N + bcol+0] : 0.f;
                    b_reg[i].y = (bcol+1 < N) ? Bm[(size_t)kk*N + bcol+1] : 0.f;
                    b_reg[i].z = (bcol+2 < N) ? Bm[(size_t)kk*N + bcol+2] : 0.f;
                    b_reg[i].w = 0.f;
                }
            }
        }

        // ---- compute: two k8 steps ----
        #pragma unroll
        for (int kk = 0; kk < 2; kk++) {
            const int kb = kk * 8;
            uint32_t bh[4][2], bl[4][2];
            #pragma unroll
            for (int ni = 0; ni < 4; ni++) {
                const int n = n_off + ni*8 + gid;
                bh[ni][0] = __float_as_uint(Bs[0][kb + tg    ][n]);
                bh[ni][1] = __float_as_uint(Bs[0][kb + 4 + tg][n]);
                bl[ni][0] = __float_as_uint(Bs[1][kb + tg    ][n]);
                bl[ni][1] = __float_as_uint(Bs[1][kb + 4 + tg][n]);
            }
            #pragma unroll
            for (int mi = 0; mi < 4; mi++) {
                const int r = m_off + mi*16 + gid;
                uint32_t ah[4], al[4];
                ah[0] = __float_as_uint(As[0][r    ][kb + tg    ]);
                ah[1] = __float_as_uint(As[0][r + 8][kb + tg    ]);
                ah[2] = __float_as_uint(As[0][r    ][kb + 4 + tg]);
                ah[3] = __float_as_uint(As[0][r + 8][kb + 4 + tg]);
                al[0] = __float_as_uint(As[1][r    ][kb + tg    ]);
                al[1] = __float_as_uint(As[1][r + 8][kb + tg    ]);
                al[2] = __float_as_uint(As[1][r    ][kb + 4 + tg]);
                al[3] = __float_as_uint(As[1][r + 8][kb + 4 + tg]);
                #pragma unroll
                for (int ni = 0; ni < 4; ni++) {
                    MMA_TF32(c[mi][ni], ah, bh[ni]);
                    MMA_TF32(c[mi][ni], ah, bl[ni]);
                    MMA_TF32(c[mi][ni], al, bh[ni]);
                }
            }
        }
        __syncthreads();
    }

    // ---- epilogue ----
    #pragma unroll
    for (int mi = 0; mi < 4; mi++) {
        #pragma unroll
        for (int half = 0; half < 2; half++) {
            const int r = row0 + m_off + mi*16 + gid + half*8;
            const int orow = (r / Tin) * Tout + toff + (r % Tin);
            #pragma unroll
            for (int ni = 0; ni < 4; ni++) {
                const int col = col0 + n_off + ni*8 + tg*2;
                if (col < N) {
                    float v0 = c[mi][ni][half*2 + 0];
                    float v1 = c[mi][ni][half*2 + 1];
                    if (bias) { v0 += bias[col]; v1 += bias[col+1]; }
                    float* dst = C + (size_t)orow * N + col;
                    if (accum) { v0 += dst[0]; v1 += dst[1]; }
                    *reinterpret_cast<float2*>(dst) = make_float2(v0, v1);
                }
            }
        }
    }
}

// ---------------- RMSNorm over last dim ----------------
__global__ void rmsnorm_k(const float* __restrict__ x, const float* __restrict__ w,
                          float* __restrict__ out, int D)
{
    __shared__ float red[32];
    const int r = blockIdx.x;
    const float* xr = x + (size_t)r * D;
    float s = 0.f;
    for (int d = threadIdx.x; d < D; d += 256) { float v = xr[d]; s = fmaf(v, v, s); }
    const float tot = block_reduce_sum_256(s, red);
    const float rms = rsqrtf(tot / (float)D + 1e-5f);
    for (int d = threadIdx.x; d < D; d += 256)
        out[(size_t)r * D + d] = xr[d] * rms * w[d];
}

// ---------------- SSD sequential scan ----------------
__global__ void scan_k(const float* __restrict__ proj,
                       const float* __restrict__ dt_bias,
                       const float* __restrict__ A_log,
                       const float* __restrict__ Dssm,
                       float* __restrict__ yraw)
{
    const int b    = blockIdx.x >> 5;
    const int h    = blockIdx.x & 31;
    const int tid  = threadIdx.x;
    const int warp = tid >> 5, lane = tid & 31;

    __shared__ float sx[PDIM];
    __shared__ float sB[NSTATE];
    __shared__ float sC[NSTATE];
    __shared__ float s_dt;

    const float dtb  = dt_bias[h];
    const float Aval = -expf(A_log[h]);
    const float Dval = Dssm[h];

    float hs[8][4];
    #pragma unroll
    for (int i = 0; i < 8; i++)
        #pragma unroll
        for (int j = 0; j < 4; j++) hs[i][j] = 0.f;

    float xprev[8];
    float bprev[4];
    float dtprev = 0.f;
    #pragma unroll
    for (int i = 0; i < 8; i++) xprev[i] = 0.f;
    #pragma unroll
    for (int j = 0; j < 4; j++) bprev[j] = 0.f;

    const int pbase = warp * 8;
    const int nbase = lane * 4;

    for (int t = 0; t < TSEQ; t++) {
        const int row = b * TSEQ + t;
        const float* pr = proj + (size_t)row * PROJ_DIM;

        if (tid < PDIM)                    sx[tid]                 = pr[DINNER + h*PDIM + tid];
        else if (tid < PDIM + NSTATE)      sB[tid - PDIM]          = pr[2*DINNER + (tid - PDIM)];
        else                               sC[tid - PDIM - NSTATE] = pr[2*DINNER + NSTATE + (tid - PDIM - NSTATE)];
        if (tid < PDIM)                    sC[(NSTATE - PDIM) + tid] = pr[2*DINNER + NSTATE + (NSTATE - PDIM) + tid];
        if (tid == 0) {
            float v = pr[2*DINNER + 2*NSTATE + h] + dtb;
            s_dt = (v > 20.f) ? v : log1pf(expf(v));   // softplus
        }
        __syncthreads();

        const float dt  = s_dt;
        const float da  = expf(dt * Aval);
        const float cu  = (1.f - ALPHA_C) * dt;
        const float cup = da * ALPHA_C * dtprev;

        float bc[4], cc[4];
        #pragma unroll
        for (int j = 0; j < 4; j++) { bc[j] = sB[nbase + j]; cc[j] = sC[nbase + j]; }

        #pragma unroll
        for (int i = 0; i < 8; i++) {
            const float xr  = sx[pbase + i];
            const float xpi = cup * xprev[i];
            const float xci = cu  * xr;
            float yp = 0.f;
            #pragma unroll
            for (int j = 0; j < 4; j++) {
                const float u = fmaf(xpi, bprev[j], xci * bc[j]);
                hs[i][j] = fmaf(da, hs[i][j], u);
                yp = fmaf(hs[i][j], cc[j], yp);
            }
            #pragma unroll
            for (int o = 16; o; o >>= 1) yp += __shfl_xor_sync(0xffffffffu, yp, o);
            if (lane == 0)
                yraw[(size_t)row * DINNER + h*PDIM + pbase + i] = fmaf(Dval, xr, yp);
            xprev[i] = xr;
        }
        #pragma unroll
        for (int j = 0; j < 4; j++) bprev[j] = bc[j];
        dtprev = dt;
        __syncthreads();
    }
}

// ---------------- y * silu(z), then rmsnorm(gnorm_w) over DINNER ----------------
__global__ void gate_gnorm_k(const float* __restrict__ proj,
                             const float* __restrict__ yraw,
                             const float* __restrict__ gw,
                             float* __restrict__ yg)
{
    __shared__ float red[32];
    const int r = blockIdx.x;
    const float* pz = proj + (size_t)r * PROJ_DIM;
    const float* yr = yraw + (size_t)r * DINNER;
    float* og = yg + (size_t)r * DINNER;

    float s = 0.f;
    for (int d = threadIdx.x; d < DINNER; d += 256) {
        const float z   = pz[d];
        const float sig = 1.f / (1.f + expf(-z));
        const float g   = yr[d] * z * sig;
        og[d] = g;
        s = fmaf(g, g, s);
    }
    const float tot = block_reduce_sum_256(s, red);
    const float rms = rsqrtf(tot / (float)DINNER + 1e-5f);
    for (int d = threadIdx.x; d < DINNER; d += 256)
        og[d] = og[d] * rms * gw[d];
}

// ---------------- mean over T per batch ----------------
__global__ void pool_k(const float* __restrict__ xin, float* __restrict__ pooled)
{
    const int b = blockIdx.x;
    for (int d = threadIdx.x; d < DMODEL; d += 256) {
        float s = 0.f;
        for (int t = 0; t < TSEQ; t++)
            s += xin[(size_t)(b*TSEQ + t) * DMODEL + d];
        pooled[b*DMODEL + d] = s * (1.f / (float)TSEQ);
    }
}

// ---------------- head GEMM + bias + L2-normalize ----------------
__global__ void head_k(const float* __restrict__ pooled,
                       const float* __restrict__ hw,
                       const float* __restrict__ hb,
                       float* __restrict__ out)
{
    __shared__ float sp[DMODEL];
    __shared__ float so[EDIM];
    __shared__ float red[32];
    const int b = blockIdx.x;

    for (int d = threadIdx.x; d < DMODEL; d += 256) sp[d] = pooled[b*DMODEL + d];
    __syncthreads();

    float acc[EDIM/256];
    #pragma unroll
    for (int m = 0; m < EDIM/256; m++) acc[m] = hb[threadIdx.x + m*256];
    for (int k = 0; k < DMODEL; k++) {
        const float p = sp[k];
        #pragma unroll
        for (int m = 0; m < EDIM/256; m++)
            acc[m] = fmaf(p, hw[(size_t)k*EDIM + threadIdx.x + m*256], acc[m]);
    }
    #pragma unroll
    for (int m = 0; m < EDIM/256; m++) so[threadIdx.x + m*256] = acc[m];
    __syncthreads();

    float s = 0.f;
    for (int e = threadIdx.x; e < EDIM; e += 256) s = fmaf(so[e], so[e], s);
    const float tot = block_reduce_sum_256(s, red);
    const float inv = 1.f / fmaxf(sqrtf(tot), 1e-12f);
    for (int e = threadIdx.x; e < EDIM; e += 256)
        out[(size_t)b*EDIM + e] = so[e] * inv;
}

// ---------------- host launcher ----------------
extern "C" void kernel_launch(void* const* d_in, const int* in_sizes, int n_in,
                              void* d_out, int out_size)
{
    const float* visual   = (const float*)d_in[0];
    const float* query    = (const float*)d_in[1];
    const float* vis_w    = (const float*)d_in[2];
    const float* vis_b    = (const float*)d_in[3];
    const float* qry_w    = (const float*)d_in[4];
    const float* qry_b    = (const float*)d_in[5];
    const float* norm_ws  = (const float*)d_in[6];
    const float* in_ws    = (const float*)d_in[7];
    const float* dt_bias  = (const float*)d_in[8];
    const float* A_logs   = (const float*)d_in[9];
    const float* D_ssm    = (const float*)d_in[10];
    const float* gnorm_ws = (const float*)d_in[11];
    const float* out_ws   = (const float*)d_in[12];
    const float* norm_f_w = (const float*)d_in[13];
    const float* head_w   = (const float*)d_in[14];
    const float* head_b   = (const float*)d_in[15];
    float* out = (float*)d_out;

    float *hidden, *xin, *proj, *yraw, *yg, *pooled;
    cudaGetSymbolAddress((void**)&hidden, g_hidden);
    cudaGetSymbolAddress((void**)&xin,    g_xin);
    cudaGetSymbolAddress((void**)&proj,   g_proj);
    cudaGetSymbolAddress((void**)&yraw,   g_yraw);
    cudaGetSymbolAddress((void**)&yg,     g_yg);
    cudaGetSymbolAddress((void**)&pooled, g_pooled);

    const dim3 blk(256);

    // initial projections into hidden[b, t, :] (row remap per batch)
    tgemm_k<<<dim3(DMODEL/128, (BATCH*TVIS)/128), blk>>>(
        visual, vis_w, hidden, BATCH*TVIS, DMODEL, DMODEL, vis_b, 0, TVIS, TSEQ, 0);
    tgemm_k<<<dim3(DMODEL/128, (BATCH*TQRY)/128), blk>>>(
        query, qry_w, hidden, BATCH*TQRY, DMODEL, DMODEL, qry_b, 0, TQRY, TSEQ, TVIS);

    for (int i = 0; i < NLAYERS; i++) {
        rmsnorm_k<<<ROWS, blk>>>(hidden, norm_ws + (size_t)i*DMODEL, xin, DMODEL);

        tgemm_k<<<dim3((PROJ_DIM + 127)/128, ROWS/128), blk>>>(
            xin, in_ws + (size_t)i*DMODEL*PROJ_DIM, proj,
            ROWS, PROJ_DIM, DMODEL, nullptr, 0, ROWS, ROWS, 0);

        scan_k<<<BATCH*NHEADS, blk>>>(
            proj, dt_bias + (size_t)i*NHEADS, A_logs + (size_t)i*NHEADS,
            D_ssm + (size_t)i*NHEADS, yraw);

        gate_gnorm_k<<<ROWS, blk>>>(proj, yraw, gnorm_ws + (size_t)i*DINNER, yg);

        tgemm_k<<<dim3(DMODEL/128, ROWS/128), blk>>>(
            yg, out_ws + (size_t)i*DINNER*DMODEL, hidden,
            ROWS, DMODEL, DINNER, nullptr, 1, ROWS, ROWS, 0);
    }

    rmsnorm_k<<<ROWS, blk>>>(hidden, norm_f_w, xin, DMODEL);
    pool_k<<<BATCH, blk>>>(xin, pooled);
    head_k<<<BATCH, blk>>>(pooled, head_w, head_b, out);
}

// round 4
// speedup vs baseline: 1.9625x; 1.3372x over previous
#include <cuda_runtime.h>
#include <cuda_fp16.h>
#include <math.h>
#include <stdint.h>

// ---------------- problem constants ----------------
#define BATCH   4
#define TSEQ    288
#define TVIS    256
#define TQRY    32
#define DMODEL  1024
#define DINNER  2048
#define NHEADS  32
#define NSTATE  128
#define PDIM    64
#define NLAYERS 12
#define PROJ_DIM 4384
#define EDIM    1536
#define ROWS    (BATCH*TSEQ)    // 1152
#define ALPHA_C 0.5f

// ---------------- scratch (device globals; no allocation) ----------------
__device__ float g_hidden[ROWS*DMODEL];
__device__ float g_xin   [ROWS*DMODEL];
__device__ float g_proj  [ROWS*PROJ_DIM];
__device__ float g_yraw  [ROWS*DINNER];
__device__ float g_yg    [ROWS*DINNER];
__device__ float g_pooled[BATCH*DMODEL];
// fp16x2 planes: A activations [M][K], B weights transposed [N][K]
__device__ __align__(16) __half g_ah[2ull*1152*2048];
__device__ __align__(16) __half g_bh[2ull*4384*1024];

// ---------------- helpers ----------------
__device__ __forceinline__ float block_reduce_sum_256(float v, float* red)
{
    #pragma unroll
    for (int o = 16; o; o >>= 1) v += __shfl_xor_sync(0xffffffffu, v, o);
    const int warp = threadIdx.x >> 5, lane = threadIdx.x & 31;
    if (lane == 0) red[warp] = v;
    __syncthreads();
    if (threadIdx.x < 32) {
        float t = (threadIdx.x < 8) ? red[threadIdx.x] : 0.f;
        #pragma unroll
        for (int o = 4; o; o >>= 1) t += __shfl_xor_sync(0xffffffffu, t, o);
        if (threadIdx.x == 0) red[0] = t;
    }
    __syncthreads();
    return red[0];
}

__device__ __forceinline__ void split2(float x, __half& h0, __half& h1)
{
    h0 = __float2half_rn(x);
    h1 = __float2half_rn(x - __half2float(h0));
}

#define MMA16(cc, aa, bb)                                                        \
  asm volatile("mma.sync.aligned.m16n8k16.row.col.f32.f16.f16.f32 "             \
    "{%0,%1,%2,%3}, {%4,%5,%6,%7}, {%8,%9}, {%0,%1,%2,%3};\n"                    \
    : "+f"((cc)[0]), "+f"((cc)[1]), "+f"((cc)[2]), "+f"((cc)[3])                 \
    : "r"((aa)[0]), "r"((aa)[1]), "r"((aa)[2]), "r"((aa)[3]),                    \
      "r"((bb)[0]), "r"((bb)[1]))

__device__ __forceinline__ void cpasync16(uint32_t dst, const void* src, int sz)
{
    asm volatile("cp.async.cg.shared.global [%0], [%1], 16, %2;\n"
                 :: "r"(dst), "l"(src), "r"(sz));
}

// swizzled fragment load: 4B at (row r, 16B-chunk ch, quad tg)
__device__ __forceinline__ uint32_t lds_frag(const char* buf, int r, int ch, int tg)
{
    return *(const uint32_t*)(buf + r*128 + (((ch) ^ (r & 7)) << 4) + tg*4);
}

// ---------------- prep: split fp32 -> 2 fp16 planes ----------------
__global__ void split2_x(const float* __restrict__ x, __half* __restrict__ out, size_t S)
{
    size_t i = (size_t)blockIdx.x * blockDim.x + threadIdx.x;
    if (i < S) {
        __half h0, h1; split2(x[i], h0, h1);
        out[i] = h0; out[S + i] = h1;
    }
}

// ---------------- prep: transpose KxN fp32 -> 2 planes [N][K] fp16 ----------------
__global__ void tsplit2(const float* __restrict__ W, __half* __restrict__ out,
                        int K, int N)
{
    __shared__ float tile[32][33];
    const int n0 = blockIdx.x * 32, k0 = blockIdx.y * 32;
    const int tx = threadIdx.x, ty = threadIdx.y;   // 32 x 8
    #pragma unroll
    for (int i = 0; i < 4; i++)
        tile[ty + i*8][tx] = W[(size_t)(k0 + ty + i*8) * N + n0 + tx];
    __syncthreads();
    const size_t NK = (size_t)N * K;
    #pragma unroll
    for (int i = 0; i < 4; i++) {
        const int n = n0 + ty + i*8;
        const int k = k0 + tx;
        __half h0, h1; split2(tile[tx][ty + i*8], h0, h1);
        out[(size_t)n * K + k]      = h0;
        out[NK + (size_t)n * K + k] = h1;
    }
}

// ---------------- fp16x2 mma.sync GEMM ----------------
// C[map(r)] (+)= A[r] @ B^T + bias.  A planes [M][K], B planes [N][K].
// M % 128 == 0, K % 64 == 0, N guarded on the B/n side.
// Tiles per stage: A0,A1,B0,B1 each 128 rows x 64 halves (128B/row, xor-swizzled).
#define PLANE_B  16384
#define STAGE_B  (4*PLANE_B)          // 64 KB
#define GSMEM    (2*STAGE_B)          // 128 KB
__global__ __launch_bounds__(256, 1)
void hgemm_k(const __half* __restrict__ Ah, size_t aplane,
             const __half* __restrict__ Bh, size_t bplane,
             float* __restrict__ C, int M, int N, int K,
             const float* __restrict__ bias, int accum,
             int Tin, int Tout, int toff)
{
    extern __shared__ char sm[];
    const uint32_t smb = (uint32_t)__cvta_generic_to_shared(sm);

    const int tid  = threadIdx.x;
    const int warp = tid >> 5, lane = tid & 31;
    const int gid  = lane >> 2, tg = lane & 3;
    const int row0 = blockIdx.y * 128;
    const int col0 = blockIdx.x * 128;
    const int m_off = (warp & 1) * 64;
    const int n_off = (warp >> 1) * 32;

    float c[4][4][4];
    #pragma unroll
    for (int mi = 0; mi < 4; mi++)
        #pragma unroll
        for (int ni = 0; ni < 4; ni++)
            #pragma unroll
            for (int q = 0; q < 4; q++) c[mi][ni][q] = 0.f;

    // load mapping: each thread: row = tid/2, 4 chunks at (tid&1)*4 + j
    const int lrow  = tid >> 1;
    const int cbase = (tid & 1) * 4;
    const int brow  = col0 + lrow;
    const int bval  = (brow < N) ? 16 : 0;
    const __half* Asrc0 = Ah + (size_t)(row0 + lrow) * K;
    const __half* Asrc1 = Asrc0 + aplane;
    const __half* Bsrc0 = Bh + (size_t)((brow < N) ? brow : 0) * K;
    const __half* Bsrc1 = Bsrc0 + bplane;
    const uint32_t drow = smb + lrow*128;

    const int nc = K >> 6;

    // prologue: stage 0
    {
        #pragma unroll
        for (int j = 0; j < 4; j++) {
            const int ch = cbase + j;
            const uint32_t sw = (uint32_t)((ch ^ (lrow & 7)) << 4);
            cpasync16(drow + 0*PLANE_B + sw, Asrc0 + ch*8, 16);
            cpasync16(drow + 1*PLANE_B + sw, Asrc1 + ch*8, 16);
            cpasync16(drow + 2*PLANE_B + sw, Bsrc0 + ch*8, bval);
            cpasync16(drow + 3*PLANE_B + sw, Bsrc1 + ch*8, bval);
        }
        asm volatile("cp.async.commit_group;\n");
    }

    for (int kc = 0; kc < nc; kc++) {
        // issue next stage
        if (kc + 1 < nc) {
            const int k0 = (kc + 1) << 6;
            const uint32_t sb = drow + ((kc + 1) & 1) * STAGE_B;
            #pragma unroll
            for (int j = 0; j < 4; j++) {
                const int ch = cbase + j;
                const uint32_t sw = (uint32_t)((ch ^ (lrow & 7)) << 4);
                cpasync16(sb + 0*PLANE_B + sw, Asrc0 + k0 + ch*8, 16);
                cpasync16(sb + 1*PLANE_B + sw, Asrc1 + k0 + ch*8, 16);
                cpasync16(sb + 2*PLANE_B + sw, Bsrc0 + k0 + ch*8, bval);
                cpasync16(sb + 3*PLANE_B + sw, Bsrc1 + k0 + ch*8, bval);
            }
        }
        asm volatile("cp.async.commit_group;\n");
        asm volatile("cp.async.wait_group 1;\n");
        __syncthreads();

        const char* st = sm + (kc & 1) * STAGE_B;
        const char* A0 = st;
        const char* A1 = st + PLANE_B;
        const char* B0 = st + 2*PLANE_B;
        const char* B1 = st + 3*PLANE_B;

        #pragma unroll
        for (int s = 0; s < 4; s++) {
            const int ch0 = 2*s, ch1 = 2*s + 1;
            uint32_t b0[4][2], b1[4][2];
            #pragma unroll
            for (int ni = 0; ni < 4; ni++) {
                const int n = n_off + ni*8 + gid;
                b0[ni][0] = lds_frag(B0, n, ch0, tg);
                b0[ni][1] = lds_frag(B0, n, ch1, tg);
                b1[ni][0] = lds_frag(B1, n, ch0, tg);
                b1[ni][1] = lds_frag(B1, n, ch1, tg);
            }
            #pragma unroll
            for (int mi = 0; mi < 4; mi++) {
                const int r = m_off + mi*16 + gid;
                uint32_t a0[4], a1[4];
                a0[0] = lds_frag(A0, r,     ch0, tg);
                a0[1] = lds_frag(A0, r + 8, ch0, tg);
                a0[2] = lds_frag(A0, r,     ch1, tg);
                a0[3] = lds_frag(A0, r + 8, ch1, tg);
                a1[0] = lds_frag(A1, r,     ch0, tg);
                a1[1] = lds_frag(A1, r + 8, ch0, tg);
                a1[2] = lds_frag(A1, r,     ch1, tg);
                a1[3] = lds_frag(A1, r + 8, ch1, tg);
                #pragma unroll
                for (int ni = 0; ni < 4; ni++) {
                    MMA16(c[mi][ni], a0, b0[ni]);
                    MMA16(c[mi][ni], a0, b1[ni]);
                    MMA16(c[mi][ni], a1, b0[ni]);
                }
            }
        }
        __syncthreads();
    }

    // ---- epilogue (same mapping as validated R2) ----
    #pragma unroll
    for (int mi = 0; mi < 4; mi++) {
        #pragma unroll
        for (int half = 0; half < 2; half++) {
            const int r = row0 + m_off + mi*16 + gid + half*8;
            const int orow = (r / Tin) * Tout + toff + (r % Tin);
            #pragma unroll
            for (int ni = 0; ni < 4; ni++) {
                const int col = col0 + n_off + ni*8 + tg*2;
                if (col < N) {
                    float v0 = c[mi][ni][half*2 + 0];
                    float v1 = c[mi][ni][half*2 + 1];
                    if (bias) { v0 += bias[col]; v1 += bias[col+1]; }
                    float* dst = C + (size_t)orow * N + col;
                    if (accum) { v0 += dst[0]; v1 += dst[1]; }
                    *reinterpret_cast<float2*>(dst) = make_float2(v0, v1);
                }
            }
        }
    }
}

// ---------------- RMSNorm over last dim ----------------
__global__ void rmsnorm_k(const float* __restrict__ x, const float* __restrict__ w,
                          float* __restrict__ out, int D)
{
    __shared__ float red[32];
    const int r = blockIdx.x;
    const float* xr = x + (size_t)r * D;
    float s = 0.f;
    for (int d = threadIdx.x; d < D; d += 256) { float v = xr[d]; s = fmaf(v, v, s); }
    const float tot = block_reduce_sum_256(s, red);
    const float rms = rsqrtf(tot / (float)D + 1e-5f);
    for (int d = threadIdx.x; d < D; d += 256)
        out[(size_t)r * D + d] = xr[d] * rms * w[d];
}

// ---------------- SSD sequential scan ----------------
__global__ void scan_k(const float* __restrict__ proj,
                       const float* __restrict__ dt_bias,
                       const float* __restrict__ A_log,
                       const float* __restrict__ Dssm,
                       float* __restrict__ yraw)
{
    const int b    = blockIdx.x >> 5;
    const int h    = blockIdx.x & 31;
    const int tid  = threadIdx.x;
    const int warp = tid >> 5, lane = tid & 31;

    __shared__ float sx[PDIM];
    __shared__ float sB[NSTATE];
    __shared__ float sC[NSTATE];
    __shared__ float s_dt;

    const float dtb  = dt_bias[h];
    const float Aval = -expf(A_log[h]);
    const float Dval = Dssm[h];

    float hs[8][4];
    #pragma unroll
    for (int i = 0; i < 8; i++)
        #pragma unroll
        for (int j = 0; j < 4; j++) hs[i][j] = 0.f;

    float xprev[8];
    float bprev[4];
    float dtprev = 0.f;
    #pragma unroll
    for (int i = 0; i < 8; i++) xprev[i] = 0.f;
    #pragma unroll
    for (int j = 0; j < 4; j++) bprev[j] = 0.f;

    const int pbase = warp * 8;
    const int nbase = lane * 4;

    for (int t = 0; t < TSEQ; t++) {
        const int row = b * TSEQ + t;
        const float* pr = proj + (size_t)row * PROJ_DIM;

        if (tid < PDIM)                    sx[tid]                 = pr[DINNER + h*PDIM + tid];
        else if (tid < PDIM + NSTATE)      sB[tid - PDIM]          = pr[2*DINNER + (tid - PDIM)];
        else                               sC[tid - PDIM - NSTATE] = pr[2*DINNER + NSTATE + (tid - PDIM - NSTATE)];
        if (tid < PDIM)                    sC[(NSTATE - PDIM) + tid] = pr[2*DINNER + NSTATE + (NSTATE - PDIM) + tid];
        if (tid == 0) {
            float v = pr[2*DINNER + 2*NSTATE + h] + dtb;
            s_dt = (v > 20.f) ? v : log1pf(expf(v));
        }
        __syncthreads();

        const float dt  = s_dt;
        const float da  = expf(dt * Aval);
        const float cu  = (1.f - ALPHA_C) * dt;
        const float cup = da * ALPHA_C * dtprev;

        float bc[4], cc[4];
        #pragma unroll
        for (int j = 0; j < 4; j++) { bc[j] = sB[nbase + j]; cc[j] = sC[nbase + j]; }

        #pragma unroll
        for (int i = 0; i < 8; i++) {
            const float xr  = sx[pbase + i];
            const float xpi = cup * xprev[i];
            const float xci = cu  * xr;
            float yp = 0.f;
            #pragma unroll
            for (int j = 0; j < 4; j++) {
                const float u = fmaf(xpi, bprev[j], xci * bc[j]);
                hs[i][j] = fmaf(da, hs[i][j], u);
                yp = fmaf(hs[i][j], cc[j], yp);
            }
            #pragma unroll
            for (int o = 16; o; o >>= 1) yp += __shfl_xor_sync(0xffffffffu, yp, o);
            if (lane == 0)
                yraw[(size_t)row * DINNER + h*PDIM + pbase + i] = fmaf(Dval, xr, yp);
            xprev[i] = xr;
        }
        #pragma unroll
        for (int j = 0; j < 4; j++) bprev[j] = bc[j];
        dtprev = dt;
        __syncthreads();
    }
}

// ---------------- y * silu(z), then rmsnorm(gnorm_w) over DINNER ----------------
__global__ void gate_gnorm_k(const float* __restrict__ proj,
                             const float* __restrict__ yraw,
                             const float* __restrict__ gw,
                             float* __restrict__ yg)
{
    __shared__ float red[32];
    const int r = blockIdx.x;
    const float* pz = proj + (size_t)r * PROJ_DIM;
    const float* yr = yraw + (size_t)r * DINNER;
    float* og = yg + (size_t)r * DINNER;

    float s = 0.f;
    for (int d = threadIdx.x; d < DINNER; d += 256) {
        const float z   = pz[d];
        const float sig = 1.f / (1.f + expf(-z));
        const float g   = yr[d] * z * sig;
        og[d] = g;
        s = fmaf(g, g, s);
    }
    const float tot = block_reduce_sum_256(s, red);
    const float rms = rsqrtf(tot / (float)DINNER + 1e-5f);
    for (int d = threadIdx.x; d < DINNER; d += 256)
        og[d] = og[d] * rms * gw[d];
}

// ---------------- mean over T per batch ----------------
__global__ void pool_k(const float* __restrict__ xin, float* __restrict__ pooled)
{
    const int b = blockIdx.x;
    for (int d = threadIdx.x; d < DMODEL; d += 256) {
        float s = 0.f;
        for (int t = 0; t < TSEQ; t++)
            s += xin[(size_t)(b*TSEQ + t) * DMODEL + d];
        pooled[b*DMODEL + d] = s * (1.f / (float)TSEQ);
    }
}

// ---------------- head GEMM + bias + L2-normalize ----------------
__global__ void head_k(const float* __restrict__ pooled,
                       const float* __restrict__ hw,
                       const float* __restrict__ hb,
                       float* __restrict__ out)
{
    __shared__ float sp[DMODEL];
    __shared__ float so[EDIM];
    __shared__ float red[32];
    const int b = blockIdx.x;

    for (int d = threadIdx.x; d < DMODEL; d += 256) sp[d] = pooled[b*DMODEL + d];
    __syncthreads();

    float acc[EDIM/256];
    #pragma unroll
    for (int m = 0; m < EDIM/256; m++) acc[m] = hb[threadIdx.x + m*256];
    for (int k = 0; k < DMODEL; k++) {
        const float p = sp[k];
        #pragma unroll
        for (int m = 0; m < EDIM/256; m++)
            acc[m] = fmaf(p, hw[(size_t)k*EDIM + threadIdx.x + m*256], acc[m]);
    }
    #pragma unroll
    for (int m = 0; m < EDIM/256; m++) so[threadIdx.x + m*256] = acc[m];
    __syncthreads();

    float s = 0.f;
    for (int e = threadIdx.x; e < EDIM; e += 256) s = fmaf(so[e], so[e], s);
    const float tot = block_reduce_sum_256(s, red);
    const float inv = 1.f / fmaxf(sqrtf(tot), 1e-12f);
    for (int e = threadIdx.x; e < EDIM; e += 256)
        out[(size_t)b*EDIM + e] = so[e] * inv;
}

// ---------------- host launcher ----------------
extern "C" void kernel_launch(void* const* d_in, const int* in_sizes, int n_in,
                              void* d_out, int out_size)
{
    const float* visual   = (const float*)d_in[0];
    const float* query    = (const float*)d_in[1];
    const float* vis_w    = (const float*)d_in[2];
    const float* vis_b    = (const float*)d_in[3];
    const float* qry_w    = (const float*)d_in[4];
    const float* qry_b    = (const float*)d_in[5];
    const float* norm_ws  = (const float*)d_in[6];
    const float* in_ws    = (const float*)d_in[7];
    const float* dt_bias  = (const float*)d_in[8];
    const float* A_logs   = (const float*)d_in[9];
    const float* D_ssm    = (const float*)d_in[10];
    const float* gnorm_ws = (const float*)d_in[11];
    const float* out_ws   = (const float*)d_in[12];
    const float* norm_f_w = (const float*)d_in[13];
    const float* head_w   = (const float*)d_in[14];
    const float* head_b   = (const float*)d_in[15];
    float* out = (float*)d_out;

    float *hidden, *xin, *proj, *yraw, *yg, *pooled;
    __half *ah, *bh;
    cudaGetSymbolAddress((void**)&hidden, g_hidden);
    cudaGetSymbolAddress((void**)&xin,    g_xin);
    cudaGetSymbolAddress((void**)&proj,   g_proj);
    cudaGetSymbolAddress((void**)&yraw,   g_yraw);
    cudaGetSymbolAddress((void**)&yg,     g_yg);
    cudaGetSymbolAddress((void**)&pooled, g_pooled);
    cudaGetSymbolAddress((void**)&ah,     g_ah);
    cudaGetSymbolAddress((void**)&bh,     g_bh);

    cudaFuncSetAttribute(hgemm_k, cudaFuncAttributeMaxDynamicSharedMemorySize, GSMEM);

    const dim3 blk(256);
    const dim3 tblk(32, 8);

    // ---- initial projections into hidden[b, t, :] (row remap per batch) ----
    {   // visual: M=1024, K=1024, N=1024
        const size_t S = (size_t)BATCH*TVIS*DMODEL;
        split2_x<<<(unsigned)((S + 255)/256), blk>>>(visual, ah, S);
        tsplit2<<<dim3(DMODEL/32, DMODEL/32), tblk>>>(vis_w, bh, DMODEL, DMODEL);
        hgemm_k<<<dim3(DMODEL/128, (BATCH*TVIS)/128), blk, GSMEM>>>(
            ah, S, bh, (size_t)DMODEL*DMODEL, hidden,
            BATCH*TVIS, DMODEL, DMODEL, vis_b, 0, TVIS, TSEQ, 0);
    }
    {   // query: M=128, K=1024, N=1024
        const size_t S = (size_t)BATCH*TQRY*DMODEL;
        split2_x<<<(unsigned)((S + 255)/256), blk>>>(query, ah, S);
        tsplit2<<<dim3(DMODEL/32, DMODEL/32), tblk>>>(qry_w, bh, DMODEL, DMODEL);
        hgemm_k<<<dim3(DMODEL/128, (BATCH*TQRY)/128), blk, GSMEM>>>(
            ah, S, bh, (size_t)DMODEL*DMODEL, hidden,
            BATCH*TQRY, DMODEL, DMODEL, qry_b, 0, TQRY, TSEQ, TVIS);
    }

    for (int i = 0; i < NLAYERS; i++) {
        rmsnorm_k<<<ROWS, blk>>>(hidden, norm_ws + (size_t)i*DMODEL, xin, DMODEL);

        {   // in-proj: M=1152, K=1024, N=4384
            const size_t S = (size_t)ROWS*DMODEL;
            split2_x<<<(unsigned)((S + 255)/256), blk>>>(xin, ah, S);
            tsplit2<<<dim3(PROJ_DIM/32, DMODEL/32), tblk>>>(
                in_ws + (size_t)i*DMODEL*PROJ_DIM, bh, DMODEL, PROJ_DIM);
            hgemm_k<<<dim3((PROJ_DIM + 127)/128, ROWS/128), blk, GSMEM>>>(
                ah, S, bh, (size_t)PROJ_DIM*DMODEL, proj,
                ROWS, PROJ_DIM, DMODEL, nullptr, 0, ROWS, ROWS, 0);
        }

        scan_k<<<BATCH*NHEADS, blk>>>(
            proj, dt_bias + (size_t)i*NHEADS, A_logs + (size_t)i*NHEADS,
            D_ssm + (size_t)i*NHEADS, yraw);

        gate_gnorm_k<<<ROWS, blk>>>(proj, yraw, gnorm_ws + (size_t)i*DINNER, yg);

        {   // out-proj (+residual): M=1152, K=2048, N=1024
            const size_t S = (size_t)ROWS*DINNER;
            split2_x<<<(unsigned)((S + 255)/256), blk>>>(yg, ah, S);
            tsplit2<<<dim3(DMODEL/32, DINNER/32), tblk>>>(
                out_ws + (size_t)i*DINNER*DMODEL, bh, DINNER, DMODEL);
            hgemm_k<<<dim3(DMODEL/128, ROWS/128), blk, GSMEM>>>(
                ah, S, bh, (size_t)DMODEL*DINNER, hidden,
                ROWS, DMODEL, DINNER, nullptr, 1, ROWS, ROWS, 0);
        }
    }

    rmsnorm_k<<<ROWS, blk>>>(hidden, norm_f_w, xin, DMODEL);
    pool_k<<<BATCH, blk>>>(xin, pooled);
    head_k<<<BATCH, blk>>>(pooled, head_w, head_b, out);
}

// round 5
// speedup vs baseline: 2.4041x; 1.2250x over previous
#include <cuda_runtime.h>
#include <cuda_fp16.h>
#include <math.h>
#include <stdint.h>

// ---------------- problem constants ----------------
#define BATCH   4
#define TSEQ    288
#define TVIS    256
#define TQRY    32
#define DMODEL  1024
#define DINNER  2048
#define NHEADS  32
#define NSTATE  128
#define PDIM    64
#define NLAYERS 12
#define PROJ_DIM 4384
#define EDIM    1536
#define ROWS    (BATCH*TSEQ)    // 1152
#define ALPHA_C 0.5f

// ---------------- scratch (device globals; no allocation) ----------------
__device__ float g_hidden[ROWS*DMODEL];
__device__ float g_xin   [ROWS*DMODEL];
__device__ float g_proj  [ROWS*PROJ_DIM];
__device__ float g_yraw  [ROWS*DINNER];
__device__ float g_pooled[BATCH*DMODEL];
// fp16x2 planes: A activations [M][K], B weights transposed [N][K]
__device__ __align__(16) __half g_ah[2ull*1152*2048];
__device__ __align__(16) __half g_bh[2ull*4384*1024];

// ---------------- helpers ----------------
__device__ __forceinline__ float block_reduce_sum_256(float v, float* red)
{
    #pragma unroll
    for (int o = 16; o; o >>= 1) v += __shfl_xor_sync(0xffffffffu, v, o);
    const int warp = threadIdx.x >> 5, lane = threadIdx.x & 31;
    if (lane == 0) red[warp] = v;
    __syncthreads();
    if (threadIdx.x < 32) {
        float t = (threadIdx.x < 8) ? red[threadIdx.x] : 0.f;
        #pragma unroll
        for (int o = 4; o; o >>= 1) t += __shfl_xor_sync(0xffffffffu, t, o);
        if (threadIdx.x == 0) red[0] = t;
    }
    __syncthreads();
    return red[0];
}

__device__ __forceinline__ void split2(float x, __half& h0, __half& h1)
{
    h0 = __float2half_rn(x);
    h1 = __float2half_rn(x - __half2float(h0));
}

#define MMA16(cc, aa, bb)                                                        \
  asm volatile("mma.sync.aligned.m16n8k16.row.col.f32.f16.f16.f32 "             \
    "{%0,%1,%2,%3}, {%4,%5,%6,%7}, {%8,%9}, {%0,%1,%2,%3};\n"                    \
    : "+f"((cc)[0]), "+f"((cc)[1]), "+f"((cc)[2]), "+f"((cc)[3])                 \
    : "r"((aa)[0]), "r"((aa)[1]), "r"((aa)[2]), "r"((aa)[3]),                    \
      "r"((bb)[0]), "r"((bb)[1]))

__device__ __forceinline__ void cpasync16(uint32_t dst, const void* src, int sz)
{
    asm volatile("cp.async.cg.shared.global [%0], [%1], 16, %2;\n"
                 :: "r"(dst), "l"(src), "r"(sz));
}
__device__ __forceinline__ void cpasync4(uint32_t dst, const void* src)
{
    asm volatile("cp.async.ca.shared.global [%0], [%1], 4;\n"
                 :: "r"(dst), "l"(src));
}

// swizzled fragment load: 4B at (row r, 16B-chunk ch, quad tg)
__device__ __forceinline__ uint32_t lds_frag(const char* buf, int r, int ch, int tg)
{
    return *(const uint32_t*)(buf + r*128 + (((ch) ^ (r & 7)) << 4) + tg*4);
}

// ---------------- prep: split fp32 -> 2 fp16 planes (inputs only) ----------------
__global__ void split2_x(const float* __restrict__ x, __half* __restrict__ out, size_t S)
{
    size_t i = (size_t)blockIdx.x * blockDim.x + threadIdx.x;
    if (i < S) {
        __half h0, h1; split2(x[i], h0, h1);
        out[i] = h0; out[S + i] = h1;
    }
}

// ---------------- prep: transpose KxN fp32 -> 2 planes [N][K] fp16 (coalesced) ----
// grid: (N/32, K/64), block 256. Tile: 64 k x 32 n.
__global__ void tsplit2f(const float* __restrict__ W, __half* __restrict__ out,
                         int K, int N)
{
    __shared__ float tile[64][33];
    const int n0 = blockIdx.x * 32, k0 = blockIdx.y * 64;
    const int tid = threadIdx.x;
    const int r = tid >> 5, c = tid & 31;
    #pragma unroll
    for (int i = 0; i < 8; i++)
        tile[i*8 + r][c] = W[(size_t)(k0 + i*8 + r) * N + n0 + c];
    __syncthreads();

    const size_t NK = (size_t)N * K;
    const int ns = tid >> 5;       // 0..7
    const int kp = tid & 31;       // half2 index along k
    #pragma unroll
    for (int j = 0; j < 4; j++) {
        const int nl = j*8 + ns;
        const int n  = n0 + nl;
        const float f0 = tile[2*kp    ][nl];
        const float f1 = tile[2*kp + 1][nl];
        __half a0, a1, b0, b1;
        split2(f0, a0, a1);
        split2(f1, b0, b1);
        __half2* p0 = (__half2*)(out + (size_t)n * K + k0);
        __half2* p1 = (__half2*)(out + NK + (size_t)n * K + k0);
        p0[kp] = __halves2half2(a0, b0);
        p1[kp] = __halves2half2(a1, b1);
    }
}

// ---------------- fp16x2 mma.sync GEMM (validated R4) ----------------
#define PLANE_B  16384
#define STAGE_B  (4*PLANE_B)
#define GSMEM    (2*STAGE_B)
__global__ __launch_bounds__(256, 1)
void hgemm_k(const __half* __restrict__ Ah, size_t aplane,
             const __half* __restrict__ Bh, size_t bplane,
             float* __restrict__ C, int M, int N, int K,
             const float* __restrict__ bias, int accum,
             int Tin, int Tout, int toff)
{
    extern __shared__ char sm[];
    const uint32_t smb = (uint32_t)__cvta_generic_to_shared(sm);

    const int tid  = threadIdx.x;
    const int warp = tid >> 5, lane = tid & 31;
    const int gid  = lane >> 2, tg = lane & 3;
    const int row0 = blockIdx.y * 128;
    const int col0 = blockIdx.x * 128;
    const int m_off = (warp & 1) * 64;
    const int n_off = (warp >> 1) * 32;

    float c[4][4][4];
    #pragma unroll
    for (int mi = 0; mi < 4; mi++)
        #pragma unroll
        for (int ni = 0; ni < 4; ni++)
            #pragma unroll
            for (int q = 0; q < 4; q++) c[mi][ni][q] = 0.f;

    const int lrow  = tid >> 1;
    const int cbase = (tid & 1) * 4;
    const int brow  = col0 + lrow;
    const int bval  = (brow < N) ? 16 : 0;
    const __half* Asrc0 = Ah + (size_t)(row0 + lrow) * K;
    const __half* Asrc1 = Asrc0 + aplane;
    const __half* Bsrc0 = Bh + (size_t)((brow < N) ? brow : 0) * K;
    const __half* Bsrc1 = Bsrc0 + bplane;
    const uint32_t drow = smb + lrow*128;

    const int nc = K >> 6;

    {
        #pragma unroll
        for (int j = 0; j < 4; j++) {
            const int ch = cbase + j;
            const uint32_t sw = (uint32_t)((ch ^ (lrow & 7)) << 4);
            cpasync16(drow + 0*PLANE_B + sw, Asrc0 + ch*8, 16);
            cpasync16(drow + 1*PLANE_B + sw, Asrc1 + ch*8, 16);
            cpasync16(drow + 2*PLANE_B + sw, Bsrc0 + ch*8, bval);
            cpasync16(drow + 3*PLANE_B + sw, Bsrc1 + ch*8, bval);
        }
        asm volatile("cp.async.commit_group;\n");
    }

    for (int kc = 0; kc < nc; kc++) {
        if (kc + 1 < nc) {
            const int k0 = (kc + 1) << 6;
            const uint32_t sb = drow + ((kc + 1) & 1) * STAGE_B;
            #pragma unroll
            for (int j = 0; j < 4; j++) {
                const int ch = cbase + j;
                const uint32_t sw = (uint32_t)((ch ^ (lrow & 7)) << 4);
                cpasync16(sb + 0*PLANE_B + sw, Asrc0 + k0 + ch*8, 16);
                cpasync16(sb + 1*PLANE_B + sw, Asrc1 + k0 + ch*8, 16);
                cpasync16(sb + 2*PLANE_B + sw, Bsrc0 + k0 + ch*8, bval);
                cpasync16(sb + 3*PLANE_B + sw, Bsrc1 + k0 + ch*8, bval);
            }
        }
        asm volatile("cp.async.commit_group;\n");
        asm volatile("cp.async.wait_group 1;\n");
        __syncthreads();

        const char* st = sm + (kc & 1) * STAGE_B;
        const char* A0 = st;
        const char* A1 = st + PLANE_B;
        const char* B0 = st + 2*PLANE_B;
        const char* B1 = st + 3*PLANE_B;

        #pragma unroll
        for (int s = 0; s < 4; s++) {
            const int ch0 = 2*s, ch1 = 2*s + 1;
            uint32_t b0[4][2], b1[4][2];
            #pragma unroll
            for (int ni = 0; ni < 4; ni++) {
                const int n = n_off + ni*8 + gid;
                b0[ni][0] = lds_frag(B0, n, ch0, tg);
                b0[ni][1] = lds_frag(B0, n, ch1, tg);
                b1[ni][0] = lds_frag(B1, n, ch0, tg);
                b1[ni][1] = lds_frag(B1, n, ch1, tg);
            }
            #pragma unroll
            for (int mi = 0; mi < 4; mi++) {
                const int r = m_off + mi*16 + gid;
                uint32_t a0[4], a1[4];
                a0[0] = lds_frag(A0, r,     ch0, tg);
                a0[1] = lds_frag(A0, r + 8, ch0, tg);
                a0[2] = lds_frag(A0, r,     ch1, tg);
                a0[3] = lds_frag(A0, r + 8, ch1, tg);
                a1[0] = lds_frag(A1, r,     ch0, tg);
                a1[1] = lds_frag(A1, r + 8, ch0, tg);
                a1[2] = lds_frag(A1, r,     ch1, tg);
                a1[3] = lds_frag(A1, r + 8, ch1, tg);
                #pragma unroll
                for (int ni = 0; ni < 4; ni++) {
                    MMA16(c[mi][ni], a0, b0[ni]);
                    MMA16(c[mi][ni], a0, b1[ni]);
                    MMA16(c[mi][ni], a1, b0[ni]);
                }
            }
        }
        __syncthreads();
    }

    #pragma unroll
    for (int mi = 0; mi < 4; mi++) {
        #pragma unroll
        for (int half = 0; half < 2; half++) {
            const int r = row0 + m_off + mi*16 + gid + half*8;
            const int orow = (r / Tin) * Tout + toff + (r % Tin);
            #pragma unroll
            for (int ni = 0; ni < 4; ni++) {
                const int col = col0 + n_off + ni*8 + tg*2;
                if (col < N) {
                    float v0 = c[mi][ni][half*2 + 0];
                    float v1 = c[mi][ni][half*2 + 1];
                    if (bias) { v0 += bias[col]; v1 += bias[col+1]; }
                    float* dst = C + (size_t)orow * N + col;
                    if (accum) { v0 += dst[0]; v1 += dst[1]; }
                    *reinterpret_cast<float2*>(dst) = make_float2(v0, v1);
                }
            }
        }
    }
}

// ---------------- RMSNorm (fp32 out, final layer) ----------------
__global__ void rmsnorm_k(const float* __restrict__ x, const float* __restrict__ w,
                          float* __restrict__ out, int D)
{
    __shared__ float red[32];
    const int r = blockIdx.x;
    const float* xr = x + (size_t)r * D;
    float s = 0.f;
    for (int d = threadIdx.x; d < D; d += 256) { float v = xr[d]; s = fmaf(v, v, s); }
    const float tot = block_reduce_sum_256(s, red);
    const float rms = rsqrtf(tot / (float)D + 1e-5f);
    for (int d = threadIdx.x; d < D; d += 256)
        out[(size_t)r * D + d] = xr[d] * rms * w[d];
}

// ---------------- RMSNorm fused with fp16x2 split (D = 1024) ----------------
__global__ void rmsnorm_split_k(const float* __restrict__ x, const float* __restrict__ w,
                                __half* __restrict__ out, size_t S)
{
    __shared__ float red[32];
    const int r = blockIdx.x;
    const int tid = threadIdx.x;
    const float4 xv = *(const float4*)(x + (size_t)r * DMODEL + tid*4);
    const float4 wv = *(const float4*)(w + tid*4);
    float s = xv.x*xv.x + xv.y*xv.y + xv.z*xv.z + xv.w*xv.w;
    const float tot = block_reduce_sum_256(s, red);
    const float rms = rsqrtf(tot / (float)DMODEL + 1e-5f);
    float v0 = xv.x*rms*wv.x, v1 = xv.y*rms*wv.y, v2 = xv.z*rms*wv.z, v3 = xv.w*rms*wv.w;
    __half h0a, h1a, h0b, h1b, h0c, h1c, h0d, h1d;
    split2(v0, h0a, h1a); split2(v1, h0b, h1b);
    split2(v2, h0c, h1c); split2(v3, h0d, h1d);
    __half2* p0 = (__half2*)(out + (size_t)r * DMODEL);
    __half2* p1 = (__half2*)(out + S + (size_t)r * DMODEL);
    p0[tid*2]   = __halves2half2(h0a, h0b);
    p0[tid*2+1] = __halves2half2(h0c, h0d);
    p1[tid*2]   = __halves2half2(h1a, h1b);
    p1[tid*2+1] = __halves2half2(h1c, h1d);
}

// ---------------- SSD scan: cp.async double-buffered ----------------
#define SCX  0
#define SCB  64
#define SCC  192
#define SCDT 320
__global__ void scan_k(const float* __restrict__ proj,
                       const float* __restrict__ dt_bias,
                       const float* __restrict__ A_log,
                       const float* __restrict__ Dssm,
                       float* __restrict__ yraw)
{
    const int b    = blockIdx.x >> 5;
    const int h    = blockIdx.x & 31;
    const int tid  = threadIdx.x;
    const int warp = tid >> 5, lane = tid & 31;

    __shared__ float st[2][324];

    const float dtb  = dt_bias[h];
    const float Aval = -expf(A_log[h]);
    const float Dval = Dssm[h];

    float hs[8][4];
    #pragma unroll
    for (int i = 0; i < 8; i++)
        #pragma unroll
        for (int j = 0; j < 4; j++) hs[i][j] = 0.f;

    float xprev[8];
    float bprev[4];
    float dtprev = 0.f;
    #pragma unroll
    for (int i = 0; i < 8; i++) xprev[i] = 0.f;
    #pragma unroll
    for (int j = 0; j < 4; j++) bprev[j] = 0.f;

    const int pbase = warp * 8;
    const int nbase = lane * 4;

    // per-thread cp.async role
    const uint32_t stb0 = (uint32_t)__cvta_generic_to_shared(&st[0][0]);
    const uint32_t stb1 = (uint32_t)__cvta_generic_to_shared(&st[1][0]);

    auto issue = [&](int buf, int t) {
        const float* pr = proj + (size_t)(b * TSEQ + t) * PROJ_DIM;
        const uint32_t base = buf ? stb1 : stb0;
        if (tid < 16)
            cpasync16(base + (SCX + tid*4)*4,  pr + DINNER + h*PDIM + tid*4, 16);
        else if (tid < 48)
            cpasync16(base + (SCB + (tid-16)*4)*4, pr + 2*DINNER + (tid-16)*4, 16);
        else if (tid < 80)
            cpasync16(base + (SCC + (tid-48)*4)*4, pr + 2*DINNER + NSTATE + (tid-48)*4, 16);
        else if (tid == 80)
            cpasync4(base + SCDT*4, pr + 2*DINNER + 2*NSTATE + h);
        asm volatile("cp.async.commit_group;\n");
    };

    issue(0, 0);

    for (int t = 0; t < TSEQ; t++) {
        asm volatile("cp.async.wait_group 0;\n");
        __syncthreads();
        if (t + 1 < TSEQ) issue((t + 1) & 1, t + 1);

        const float* sb = st[t & 1];
        const float vdt = sb[SCDT] + dtb;
        const float dt  = (vdt > 20.f) ? vdt : log1pf(expf(vdt));
        const float da  = expf(dt * Aval);
        const float cu  = (1.f - ALPHA_C) * dt;
        const float cup = da * ALPHA_C * dtprev;

        float bc[4], cc[4];
        #pragma unroll
        for (int j = 0; j < 4; j++) { bc[j] = sb[SCB + nbase + j]; cc[j] = sb[SCC + nbase + j]; }

        const int row = b * TSEQ + t;
        #pragma unroll
        for (int i = 0; i < 8; i++) {
            const float xr  = sb[SCX + pbase + i];
            const float xpi = cup * xprev[i];
            const float xci = cu  * xr;
            float yp = 0.f;
            #pragma unroll
            for (int j = 0; j < 4; j++) {
                const float u = fmaf(xpi, bprev[j], xci * bc[j]);
                hs[i][j] = fmaf(da, hs[i][j], u);
                yp = fmaf(hs[i][j], cc[j], yp);
            }
            #pragma unroll
            for (int o = 16; o; o >>= 1) yp += __shfl_xor_sync(0xffffffffu, yp, o);
            if (lane == 0)
                yraw[(size_t)row * DINNER + h*PDIM + pbase + i] = fmaf(Dval, xr, yp);
            xprev[i] = xr;
        }
        #pragma unroll
        for (int j = 0; j < 4; j++) bprev[j] = bc[j];
        dtprev = dt;
    }
}

// ---------------- gate + gnorm fused with fp16x2 split (D = 2048) ----------------
__global__ void gate_gnorm_split_k(const float* __restrict__ proj,
                                   const float* __restrict__ yraw,
                                   const float* __restrict__ gw,
                                   __half* __restrict__ out, size_t S)
{
    __shared__ float red[32];
    __shared__ float gbuf[DINNER];
    const int r = blockIdx.x;
    const int tid = threadIdx.x;
    const float* pz = proj + (size_t)r * PROJ_DIM;
    const float* yr = yraw + (size_t)r * DINNER;

    float s = 0.f;
    #pragma unroll
    for (int it = 0; it < 2; it++) {
        const int d = (tid + it*256) * 4;
        const float4 zv = *(const float4*)(pz + d);
        const float4 yv = *(const float4*)(yr + d);
        float g0 = yv.x * zv.x / (1.f + expf(-zv.x));
        float g1 = yv.y * zv.y / (1.f + expf(-zv.y));
        float g2 = yv.z * zv.z / (1.f + expf(-zv.z));
        float g3 = yv.w * zv.w / (1.f + expf(-zv.w));
        gbuf[d+0] = g0; gbuf[d+1] = g1; gbuf[d+2] = g2; gbuf[d+3] = g3;
        s += g0*g0 + g1*g1 + g2*g2 + g3*g3;
    }
    const float tot = block_reduce_sum_256(s, red);
    const float rms = rsqrtf(tot / (float)DINNER + 1e-5f);

    __half2* p0 = (__half2*)(out + (size_t)r * DINNER);
    __half2* p1 = (__half2*)(out + S + (size_t)r * DINNER);
    #pragma unroll
    for (int it = 0; it < 2; it++) {
        const int d = (tid + it*256) * 4;
        const float4 wv = *(const float4*)(gw + d);
        float v0 = gbuf[d+0]*rms*wv.x, v1 = gbuf[d+1]*rms*wv.y;
        float v2 = gbuf[d+2]*rms*wv.z, v3 = gbuf[d+3]*rms*wv.w;
        __half h0a, h1a, h0b, h1b, h0c, h1c, h0d, h1d;
        split2(v0, h0a, h1a); split2(v1, h0b, h1b);
        split2(v2, h0c, h1c); split2(v3, h0d, h1d);
        p0[d/2]   = __halves2half2(h0a, h0b);
        p0[d/2+1] = __halves2half2(h0c, h0d);
        p1[d/2]   = __halves2half2(h1a, h1b);
        p1[d/2+1] = __halves2half2(h1c, h1d);
    }
}

// ---------------- mean over T per batch ----------------
__global__ void pool_k(const float* __restrict__ xin, float* __restrict__ pooled)
{
    const int b = blockIdx.x;
    const int d = blockIdx.y * 256 + threadIdx.x;
    float s = 0.f;
    for (int t = 0; t < TSEQ; t++)
        s += xin[(size_t)(b*TSEQ + t) * DMODEL + d];
    pooled[b*DMODEL + d] = s * (1.f / (float)TSEQ);
}

// ---------------- head GEMM + bias + L2-normalize ----------------
__global__ void head_k(const float* __restrict__ pooled,
                       const float* __restrict__ hw,
                       const float* __restrict__ hb,
                       float* __restrict__ out)
{
    __shared__ float sp[DMODEL];
    __shared__ float so[EDIM];
    __shared__ float red[32];
    const int b = blockIdx.x;

    for (int d = threadIdx.x; d < DMODEL; d += 256) sp[d] = pooled[b*DMODEL + d];
    __syncthreads();

    float acc[EDIM/256];
    #pragma unroll
    for (int m = 0; m < EDIM/256; m++) acc[m] = hb[threadIdx.x + m*256];
    for (int k = 0; k < DMODEL; k++) {
        const float p = sp[k];
        #pragma unroll
        for (int m = 0; m < EDIM/256; m++)
            acc[m] = fmaf(p, hw[(size_t)k*EDIM + threadIdx.x + m*256], acc[m]);
    }
    #pragma unroll
    for (int m = 0; m < EDIM/256; m++) so[threadIdx.x + m*256] = acc[m];
    __syncthreads();

    float s = 0.f;
    for (int e = threadIdx.x; e < EDIM; e += 256) s = fmaf(so[e], so[e], s);
    const float tot = block_reduce_sum_256(s, red);
    const float inv = 1.f / fmaxf(sqrtf(tot), 1e-12f);
    for (int e = threadIdx.x; e < EDIM; e += 256)
        out[(size_t)b*EDIM + e] = so[e] * inv;
}

// ---------------- host launcher ----------------
extern "C" void kernel_launch(void* const* d_in, const int* in_sizes, int n_in,
                              void* d_out, int out_size)
{
    const float* visual   = (const float*)d_in[0];
    const float* query    = (const float*)d_in[1];
    const float* vis_w    = (const float*)d_in[2];
    const float* vis_b    = (const float*)d_in[3];
    const float* qry_w    = (const float*)d_in[4];
    const float* qry_b    = (const float*)d_in[5];
    const float* norm_ws  = (const float*)d_in[6];
    const float* in_ws    = (const float*)d_in[7];
    const float* dt_bias  = (const float*)d_in[8];
    const float* A_logs   = (const float*)d_in[9];
    const float* D_ssm    = (const float*)d_in[10];
    const float* gnorm_ws = (const float*)d_in[11];
    const float* out_ws   = (const float*)d_in[12];
    const float* norm_f_w = (const float*)d_in[13];
    const float* head_w   = (const float*)d_in[14];
    const float* head_b   = (const float*)d_in[15];
    float* out = (float*)d_out;

    float *hidden, *xin, *proj, *yraw, *pooled;
    __half *ah, *bh;
    cudaGetSymbolAddress((void**)&hidden, g_hidden);
    cudaGetSymbolAddress((void**)&xin,    g_xin);
    cudaGetSymbolAddress((void**)&proj,   g_proj);
    cudaGetSymbolAddress((void**)&yraw,   g_yraw);
    cudaGetSymbolAddress((void**)&pooled, g_pooled);
    cudaGetSymbolAddress((void**)&ah,     g_ah);
    cudaGetSymbolAddress((void**)&bh,     g_bh);

    cudaFuncSetAttribute(hgemm_k, cudaFuncAttributeMaxDynamicSharedMemorySize, GSMEM);

    const dim3 blk(256);

    // ---- initial projections into hidden[b, t, :] ----
    {   // visual
        const size_t S = (size_t)BATCH*TVIS*DMODEL;
        split2_x<<<(unsigned)((S + 255)/256), blk>>>(visual, ah, S);
        tsplit2f<<<dim3(DMODEL/32, DMODEL/64), blk>>>(vis_w, bh, DMODEL, DMODEL);
        hgemm_k<<<dim3(DMODEL/128, (BATCH*TVIS)/128), blk, GSMEM>>>(
            ah, S, bh, (size_t)DMODEL*DMODEL, hidden,
            BATCH*TVIS, DMODEL, DMODEL, vis_b, 0, TVIS, TSEQ, 0);
    }
    {   // query
        const size_t S = (size_t)BATCH*TQRY*DMODEL;
        split2_x<<<(unsigned)((S + 255)/256), blk>>>(query, ah, S);
        tsplit2f<<<dim3(DMODEL/32, DMODEL/64), blk>>>(qry_w, bh, DMODEL, DMODEL);
        hgemm_k<<<dim3(DMODEL/128, (BATCH*TQRY)/128), blk, GSMEM>>>(
            ah, S, bh, (size_t)DMODEL*DMODEL, hidden,
            BATCH*TQRY, DMODEL, DMODEL, qry_b, 0, TQRY, TSEQ, TVIS);
    }

    for (int i = 0; i < NLAYERS; i++) {
        const size_t SA = (size_t)ROWS*DMODEL;
        rmsnorm_split_k<<<ROWS, blk>>>(hidden, norm_ws + (size_t)i*DMODEL, ah, SA);

        tsplit2f<<<dim3(PROJ_DIM/32, DMODEL/64), blk>>>(
            in_ws + (size_t)i*DMODEL*PROJ_DIM, bh, DMODEL, PROJ_DIM);
        hgemm_k<<<dim3((PROJ_DIM + 127)/128, ROWS/128), blk, GSMEM>>>(
            ah, SA, bh, (size_t)PROJ_DIM*DMODEL, proj,
            ROWS, PROJ_DIM, DMODEL, nullptr, 0, ROWS, ROWS, 0);

        scan_k<<<BATCH*NHEADS, blk>>>(
            proj, dt_bias + (size_t)i*NHEADS, A_logs + (size_t)i*NHEADS,
            D_ssm + (size_t)i*NHEADS, yraw);

        const size_t SG = (size_t)ROWS*DINNER;
        gate_gnorm_split_k<<<ROWS, blk>>>(proj, yraw, gnorm_ws + (size_t)i*DINNER, ah, SG);

        tsplit2f<<<dim3(DMODEL/32, DINNER/64), blk>>>(
            out_ws + (size_t)i*DINNER*DMODEL, bh, DINNER, DMODEL);
        hgemm_k<<<dim3(DMODEL/128, ROWS/128), blk, GSMEM>>>(
            ah, SG, bh, (size_t)DMODEL*DINNER, hidden,
            ROWS, DMODEL, DINNER, nullptr, 1, ROWS, ROWS, 0);
    }

    rmsnorm_k<<<ROWS, blk>>>(hidden, norm_f_w, xin, DMODEL);
    pool_k<<<dim3(BATCH, DMODEL/256), blk>>>(xin, pooled);
    head_k<<<BATCH, blk>>>(pooled, head_w, head_b, out);
}

// round 6
// speedup vs baseline: 2.6475x; 1.1013x over previous
#include <cuda_runtime.h>
#include <cuda_fp16.h>
#include <math.h>
#include <stdint.h>

// ---------------- problem constants ----------------
#define BATCH   4
#define TSEQ    288
#define TVIS    256
#define TQRY    32
#define DMODEL  1024
#define DINNER  2048
#define NHEADS  32
#define NSTATE  128
#define PDIM    64
#define NLAYERS 12
#define PROJ_DIM 4384
#define EDIM    1536
#define ROWS    (BATCH*TSEQ)    // 1152
#define ALPHA_C 0.5f

// ---------------- scratch (device globals; no allocation) ----------------
__device__ float g_hidden[ROWS*DMODEL];
__device__ float g_xin   [ROWS*DMODEL];
__device__ float g_proj  [ROWS*PROJ_DIM];
__device__ float g_yraw  [ROWS*DINNER];
__device__ float g_pooled[BATCH*DMODEL];
__device__ __align__(16) __half g_ah[2ull*1152*2048];
__device__ __align__(16) __half g_bh[2ull*4384*1024];

// ---------------- helpers ----------------
__device__ __forceinline__ float block_reduce_sum_256(float v, float* red)
{
    #pragma unroll
    for (int o = 16; o; o >>= 1) v += __shfl_xor_sync(0xffffffffu, v, o);
    const int warp = threadIdx.x >> 5, lane = threadIdx.x & 31;
    if (lane == 0) red[warp] = v;
    __syncthreads();
    if (threadIdx.x < 32) {
        float t = (threadIdx.x < 8) ? red[threadIdx.x] : 0.f;
        #pragma unroll
        for (int o = 4; o; o >>= 1) t += __shfl_xor_sync(0xffffffffu, t, o);
        if (threadIdx.x == 0) red[0] = t;
    }
    __syncthreads();
    return red[0];
}

__device__ __forceinline__ void split2(float x, __half& h0, __half& h1)
{
    h0 = __float2half_rn(x);
    h1 = __float2half_rn(x - __half2float(h0));
}

#define MMA16(cc, aa, bb)                                                        \
  asm volatile("mma.sync.aligned.m16n8k16.row.col.f32.f16.f16.f32 "             \
    "{%0,%1,%2,%3}, {%4,%5,%6,%7}, {%8,%9}, {%0,%1,%2,%3};\n"                    \
    : "+f"((cc)[0]), "+f"((cc)[1]), "+f"((cc)[2]), "+f"((cc)[3])                 \
    : "r"((aa)[0]), "r"((aa)[1]), "r"((aa)[2]), "r"((aa)[3]),                    \
      "r"((bb)[0]), "r"((bb)[1]))

__device__ __forceinline__ void ldsm4(uint32_t* r, uint32_t addr)
{
    asm volatile("ldmatrix.sync.aligned.m8n8.x4.shared.b16 {%0,%1,%2,%3}, [%4];"
                 : "=r"(r[0]), "=r"(r[1]), "=r"(r[2]), "=r"(r[3]) : "r"(addr));
}
__device__ __forceinline__ void ldsm2(uint32_t* r, uint32_t addr)
{
    asm volatile("ldmatrix.sync.aligned.m8n8.x2.shared.b16 {%0,%1}, [%2];"
                 : "=r"(r[0]), "=r"(r[1]) : "r"(addr));
}

__device__ __forceinline__ void cpasync16(uint32_t dst, const void* src, int sz)
{
    asm volatile("cp.async.cg.shared.global [%0], [%1], 16, %2;\n"
                 :: "r"(dst), "l"(src), "r"(sz));
}
__device__ __forceinline__ void cpasync4(uint32_t dst, const void* src)
{
    asm volatile("cp.async.ca.shared.global [%0], [%1], 4;\n"
                 :: "r"(dst), "l"(src));
}

// ---------------- prep: split fp32 -> 2 fp16 planes (inputs only) ----------------
__global__ void split2_x(const float* __restrict__ x, __half* __restrict__ out, size_t S)
{
    size_t i = (size_t)blockIdx.x * blockDim.x + threadIdx.x;
    if (i < S) {
        __half h0, h1; split2(x[i], h0, h1);
        out[i] = h0; out[S + i] = h1;
    }
}

// ---------------- prep: transpose KxN fp32 -> 2 planes [N][K] fp16 ----------------
__global__ void tsplit2f(const float* __restrict__ W, __half* __restrict__ out,
                         int K, int N)
{
    __shared__ float tile[64][33];
    const int n0 = blockIdx.x * 32, k0 = blockIdx.y * 64;
    const int tid = threadIdx.x;
    const int r = tid >> 5, c = tid & 31;
    #pragma unroll
    for (int i = 0; i < 8; i++)
        tile[i*8 + r][c] = W[(size_t)(k0 + i*8 + r) * N + n0 + c];
    __syncthreads();

    const size_t NK = (size_t)N * K;
    const int ns = tid >> 5;
    const int kp = tid & 31;
    #pragma unroll
    for (int j = 0; j < 4; j++) {
        const int nl = j*8 + ns;
        const int n  = n0 + nl;
        const float f0 = tile[2*kp    ][nl];
        const float f1 = tile[2*kp + 1][nl];
        __half a0, a1, b0, b1;
        split2(f0, a0, a1);
        split2(f1, b0, b1);
        __half2* p0 = (__half2*)(out + (size_t)n * K + k0);
        __half2* p1 = (__half2*)(out + NK + (size_t)n * K + k0);
        p0[kp] = __halves2half2(a0, b0);
        p1[kp] = __halves2half2(a1, b1);
    }
}

// ---------------- fp16x2 mma.sync GEMM with ldmatrix, templated M tile ----------
// C[map(r)] (+)= A[r] @ B^T + bias.  A planes [M][K], B planes [N][K].
// M % BM == 0, K % 64 == 0, N guarded.
#define BPLANE 16384
template<int BM>
__global__ __launch_bounds__(256, 1)
void hgemm_t(const __half* __restrict__ Ah, size_t aplane,
             const __half* __restrict__ Bh, size_t bplane,
             float* __restrict__ C, int M, int N, int K,
             const float* __restrict__ bias, int accum,
             int Tin, int Tout, int toff)
{
    constexpr int MI     = BM / 32;          // 4 (BM=128) or 2 (BM=64)
    constexpr int APLANE = BM * 128;         // bytes per A plane per stage
    constexpr int STAGE  = 2*APLANE + 2*BPLANE;
    constexpr int APT    = BM / 32;          // A chunks per thread
    constexpr int TPR    = 8 / APT;          // threads per A row

    extern __shared__ char sm[];
    const uint32_t smb = (uint32_t)__cvta_generic_to_shared(sm);

    const int tid  = threadIdx.x;
    const int warp = tid >> 5, lane = tid & 31;
    const int gid  = lane >> 2, tg = lane & 3;
    const int row0 = blockIdx.y * BM;
    const int col0 = blockIdx.x * 128;
    const int m_off = (warp & 1) * (BM/2);
    const int n_off = (warp >> 1) * 32;

    float c[MI][4][4];
    #pragma unroll
    for (int mi = 0; mi < MI; mi++)
        #pragma unroll
        for (int ni = 0; ni < 4; ni++)
            #pragma unroll
            for (int q = 0; q < 4; q++) c[mi][ni][q] = 0.f;

    // ---- global->smem load mapping ----
    const int larow  = tid / TPR;
    const int cbase  = (tid % TPR) * APT;
    const int lbrow  = tid >> 1;
    const int cbaseB = (tid & 1) * 4;
    const int brow   = col0 + lbrow;
    const int bval   = (brow < N) ? 16 : 0;
    const __half* Asrc0 = Ah + (size_t)(row0 + larow) * K;
    const __half* Asrc1 = Asrc0 + aplane;
    const __half* Bsrc0 = Bh + (size_t)((brow < N) ? brow : 0) * K;
    const __half* Bsrc1 = Bsrc0 + bplane;

    // ---- ldmatrix per-lane address invariants ----
    const int la   = lane & 15;
    const int asel = lane >> 4;          // chunk add for A x4
    const int lb   = lane & 7;
    const int bsel = (lane >> 3) & 1;    // chunk add for B x2
    uint32_t aoff[MI]; int ar7[MI];
    #pragma unroll
    for (int mi = 0; mi < MI; mi++) {
        const int r = m_off + mi*16 + la;
        aoff[mi] = (uint32_t)r * 128;
        ar7[mi]  = r & 7;
    }
    uint32_t boff[4]; int br7[4];
    #pragma unroll
    for (int ni = 0; ni < 4; ni++) {
        const int r = n_off + ni*8 + lb;
        boff[ni] = (uint32_t)r * 128;
        br7[ni]  = r & 7;
    }

    const int nc = K >> 6;

    // ---- prologue ----
    {
        const uint32_t sb = smb;
        #pragma unroll
        for (int j = 0; j < APT; j++) {
            const int ch = cbase + j;
            const uint32_t sw = (uint32_t)((ch ^ (larow & 7)) << 4);
            cpasync16(sb + larow*128 + sw,          Asrc0 + ch*8, 16);
            cpasync16(sb + APLANE + larow*128 + sw, Asrc1 + ch*8, 16);
        }
        #pragma unroll
        for (int j = 0; j < 4; j++) {
            const int ch = cbaseB + j;
            const uint32_t sw = (uint32_t)((ch ^ (lbrow & 7)) << 4);
            cpasync16(sb + 2*APLANE + lbrow*128 + sw,          Bsrc0 + ch*8, bval);
            cpasync16(sb + 2*APLANE + BPLANE + lbrow*128 + sw, Bsrc1 + ch*8, bval);
        }
        asm volatile("cp.async.commit_group;\n");
    }

    for (int kc = 0; kc < nc; kc++) {
        if (kc + 1 < nc) {
            const int k0 = (kc + 1) << 6;
            const uint32_t sb = smb + ((kc + 1) & 1) * STAGE;
            #pragma unroll
            for (int j = 0; j < APT; j++) {
                const int ch = cbase + j;
                const uint32_t sw = (uint32_t)((ch ^ (larow & 7)) << 4);
                cpasync16(sb + larow*128 + sw,          Asrc0 + k0 + ch*8, 16);
                cpasync16(sb + APLANE + larow*128 + sw, Asrc1 + k0 + ch*8, 16);
            }
            #pragma unroll
            for (int j = 0; j < 4; j++) {
                const int ch = cbaseB + j;
                const uint32_t sw = (uint32_t)((ch ^ (lbrow & 7)) << 4);
                cpasync16(sb + 2*APLANE + lbrow*128 + sw,          Bsrc0 + k0 + ch*8, bval);
                cpasync16(sb + 2*APLANE + BPLANE + lbrow*128 + sw, Bsrc1 + k0 + ch*8, bval);
            }
        }
        asm volatile("cp.async.commit_group;\n");
        asm volatile("cp.async.wait_group 1;\n");
        __syncthreads();

        const uint32_t S0 = smb + (kc & 1) * STAGE;           // A0
        const uint32_t S1 = S0 + APLANE;                      // A1
        const uint32_t S2 = S0 + 2*APLANE;                    // B0
        const uint32_t S3 = S2 + BPLANE;                      // B1

        #pragma unroll
        for (int s = 0; s < 4; s++) {
            uint32_t b0[4][2], b1[4][2];
            #pragma unroll
            for (int ni = 0; ni < 4; ni++) {
                const uint32_t swb = (uint32_t)(((2*s + bsel) ^ br7[ni]) << 4);
                ldsm2(b0[ni], S2 + boff[ni] + swb);
                ldsm2(b1[ni], S3 + boff[ni] + swb);
            }
            #pragma unroll
            for (int mi = 0; mi < MI; mi++) {
                const uint32_t swa = (uint32_t)(((2*s + asel) ^ ar7[mi]) << 4);
                uint32_t a0[4], a1[4];
                ldsm4(a0, S0 + aoff[mi] + swa);
                ldsm4(a1, S1 + aoff[mi] + swa);
                #pragma unroll
                for (int ni = 0; ni < 4; ni++) {
                    MMA16(c[mi][ni], a0, b0[ni]);
                    MMA16(c[mi][ni], a0, b1[ni]);
                    MMA16(c[mi][ni], a1, b0[ni]);
                }
            }
        }
        __syncthreads();
    }

    // ---- epilogue ----
    #pragma unroll
    for (int mi = 0; mi < MI; mi++) {
        #pragma unroll
        for (int half = 0; half < 2; half++) {
            const int r = row0 + m_off + mi*16 + gid + half*8;
            const int orow = (r / Tin) * Tout + toff + (r % Tin);
            #pragma unroll
            for (int ni = 0; ni < 4; ni++) {
                const int col = col0 + n_off + ni*8 + tg*2;
                if (col < N) {
                    float v0 = c[mi][ni][half*2 + 0];
                    float v1 = c[mi][ni][half*2 + 1];
                    if (bias) { v0 += bias[col]; v1 += bias[col+1]; }
                    float* dst = C + (size_t)orow * N + col;
                    if (accum) { v0 += dst[0]; v1 += dst[1]; }
                    *reinterpret_cast<float2*>(dst) = make_float2(v0, v1);
                }
            }
        }
    }
}

#define GSMEM128 (2*(2*128*128 + 2*BPLANE))   // 131072
#define GSMEM64  (2*(2*64*128  + 2*BPLANE))   // 98304

// ---------------- RMSNorm (fp32 out, final layer) ----------------
__global__ void rmsnorm_k(const float* __restrict__ x, const float* __restrict__ w,
                          float* __restrict__ out, int D)
{
    __shared__ float red[32];
    const int r = blockIdx.x;
    const float* xr = x + (size_t)r * D;
    float s = 0.f;
    for (int d = threadIdx.x; d < D; d += 256) { float v = xr[d]; s = fmaf(v, v, s); }
    const float tot = block_reduce_sum_256(s, red);
    const float rms = rsqrtf(tot / (float)D + 1e-5f);
    for (int d = threadIdx.x; d < D; d += 256)
        out[(size_t)r * D + d] = xr[d] * rms * w[d];
}

// ---------------- RMSNorm fused with fp16x2 split (D = 1024) ----------------
__global__ void rmsnorm_split_k(const float* __restrict__ x, const float* __restrict__ w,
                                __half* __restrict__ out, size_t S)
{
    __shared__ float red[32];
    const int r = blockIdx.x;
    const int tid = threadIdx.x;
    const float4 xv = *(const float4*)(x + (size_t)r * DMODEL + tid*4);
    const float4 wv = *(const float4*)(w + tid*4);
    float s = xv.x*xv.x + xv.y*xv.y + xv.z*xv.z + xv.w*xv.w;
    const float tot = block_reduce_sum_256(s, red);
    const float rms = rsqrtf(tot / (float)DMODEL + 1e-5f);
    float v0 = xv.x*rms*wv.x, v1 = xv.y*rms*wv.y, v2 = xv.z*rms*wv.z, v3 = xv.w*rms*wv.w;
    __half h0a, h1a, h0b, h1b, h0c, h1c, h0d, h1d;
    split2(v0, h0a, h1a); split2(v1, h0b, h1b);
    split2(v2, h0c, h1c); split2(v3, h0d, h1d);
    __half2* p0 = (__half2*)(out + (size_t)r * DMODEL);
    __half2* p1 = (__half2*)(out + S + (size_t)r * DMODEL);
    p0[tid*2]   = __halves2half2(h0a, h0b);
    p0[tid*2+1] = __halves2half2(h0c, h0d);
    p1[tid*2]   = __halves2half2(h1a, h1b);
    p1[tid*2+1] = __halves2half2(h1c, h1d);
}

// ---------------- SSD scan: 3-deep cp.async pipeline ----------------
#define SCX  0
#define SCB  64
#define SCC  192
#define SCDT 320
__global__ void scan_k(const float* __restrict__ proj,
                       const float* __restrict__ dt_bias,
                       const float* __restrict__ A_log,
                       const float* __restrict__ Dssm,
                       float* __restrict__ yraw)
{
    const int b    = blockIdx.x >> 5;
    const int h    = blockIdx.x & 31;
    const int tid  = threadIdx.x;
    const int warp = tid >> 5, lane = tid & 31;

    __shared__ float st[3][324];

    const float dtb  = dt_bias[h];
    const float Aval = -expf(A_log[h]);
    const float Dval = Dssm[h];

    float hs[8][4];
    #pragma unroll
    for (int i = 0; i < 8; i++)
        #pragma unroll
        for (int j = 0; j < 4; j++) hs[i][j] = 0.f;

    float xprev[8];
    float bprev[4];
    float dtprev = 0.f;
    #pragma unroll
    for (int i = 0; i < 8; i++) xprev[i] = 0.f;
    #pragma unroll
    for (int j = 0; j < 4; j++) bprev[j] = 0.f;

    const int pbase = warp * 8;
    const int nbase = lane * 4;

    uint32_t stb[3];
    stb[0] = (uint32_t)__cvta_generic_to_shared(&st[0][0]);
    stb[1] = (uint32_t)__cvta_generic_to_shared(&st[1][0]);
    stb[2] = (uint32_t)__cvta_generic_to_shared(&st[2][0]);

    auto issue = [&](int buf, int t) {
        const float* pr = proj + (size_t)(b * TSEQ + t) * PROJ_DIM;
        const uint32_t base = stb[buf];
        if (tid < 16)
            cpasync16(base + (SCX + tid*4)*4,  pr + DINNER + h*PDIM + tid*4, 16);
        else if (tid < 48)
            cpasync16(base + (SCB + (tid-16)*4)*4, pr + 2*DINNER + (tid-16)*4, 16);
        else if (tid < 80)
            cpasync16(base + (SCC + (tid-48)*4)*4, pr + 2*DINNER + NSTATE + (tid-48)*4, 16);
        else if (tid == 80)
            cpasync4(base + SCDT*4, pr + 2*DINNER + 2*NSTATE + h);
        asm volatile("cp.async.commit_group;\n");
    };

    issue(0, 0);
    issue(1, 1);

    int buf = 0;
    for (int t = 0; t < TSEQ; t++) {
        asm volatile("cp.async.wait_group 1;\n");
        __syncthreads();
        if (t + 2 < TSEQ) {
            int nb = buf + 2; if (nb >= 3) nb -= 3;
            issue(nb, t + 2);
        } else {
            asm volatile("cp.async.commit_group;\n");
        }

        const float* sb = st[buf];
        const float vdt = sb[SCDT] + dtb;
        const float dt  = (vdt > 20.f) ? vdt : log1pf(expf(vdt));
        const float da  = expf(dt * Aval);
        const float cu  = (1.f - ALPHA_C) * dt;
        const float cup = da * ALPHA_C * dtprev;

        float bc[4], cc[4];
        #pragma unroll
        for (int j = 0; j < 4; j++) { bc[j] = sb[SCB + nbase + j]; cc[j] = sb[SCC + nbase + j]; }

        const int row = b * TSEQ + t;
        #pragma unroll
        for (int i = 0; i < 8; i++) {
            const float xr  = sb[SCX + pbase + i];
            const float xpi = cup * xprev[i];
            const float xci = cu  * xr;
            float yp = 0.f;
            #pragma unroll
            for (int j = 0; j < 4; j++) {
                const float u = fmaf(xpi, bprev[j], xci * bc[j]);
                hs[i][j] = fmaf(da, hs[i][j], u);
                yp = fmaf(hs[i][j], cc[j], yp);
            }
            #pragma unroll
            for (int o = 16; o; o >>= 1) yp += __shfl_xor_sync(0xffffffffu, yp, o);
            if (lane == 0)
                yraw[(size_t)row * DINNER + h*PDIM + pbase + i] = fmaf(Dval, xr, yp);
            xprev[i] = xr;
        }
        #pragma unroll
        for (int j = 0; j < 4; j++) bprev[j] = bc[j];
        dtprev = dt;
        buf++; if (buf >= 3) buf = 0;
    }
}

// ---------------- gate + gnorm fused with fp16x2 split (D = 2048) ----------------
__global__ void gate_gnorm_split_k(const float* __restrict__ proj,
                                   const float* __restrict__ yraw,
                                   const float* __restrict__ gw,
                                   __half* __restrict__ out, size_t S)
{
    __shared__ float red[32];
    __shared__ float gbuf[DINNER];
    const int r = blockIdx.x;
    const int tid = threadIdx.x;
    const float* pz = proj + (size_t)r * PROJ_DIM;
    const float* yr = yraw + (size_t)r * DINNER;

    float s = 0.f;
    #pragma unroll
    for (int it = 0; it < 2; it++) {
        const int d = (tid + it*256) * 4;
        const float4 zv = *(const float4*)(pz + d);
        const float4 yv = *(const float4*)(yr + d);
        float g0 = yv.x * zv.x / (1.f + expf(-zv.x));
        float g1 = yv.y * zv.y / (1.f + expf(-zv.y));
        float g2 = yv.z * zv.z / (1.f + expf(-zv.z));
        float g3 = yv.w * zv.w / (1.f + expf(-zv.w));
        gbuf[d+0] = g0; gbuf[d+1] = g1; gbuf[d+2] = g2; gbuf[d+3] = g3;
        s += g0*g0 + g1*g1 + g2*g2 + g3*g3;
    }
    const float tot = block_reduce_sum_256(s, red);
    const float rms = rsqrtf(tot / (float)DINNER + 1e-5f);

    __half2* p0 = (__half2*)(out + (size_t)r * DINNER);
    __half2* p1 = (__half2*)(out + S + (size_t)r * DINNER);
    #pragma unroll
    for (int it = 0; it < 2; it++) {
        const int d = (tid + it*256) * 4;
        const float4 wv = *(const float4*)(gw + d);
        float v0 = gbuf[d+0]*rms*wv.x, v1 = gbuf[d+1]*rms*wv.y;
        float v2 = gbuf[d+2]*rms*wv.z, v3 = gbuf[d+3]*rms*wv.w;
        __half h0a, h1a, h0b, h1b, h0c, h1c, h0d, h1d;
        split2(v0, h0a, h1a); split2(v1, h0b, h1b);
        split2(v2, h0c, h1c); split2(v3, h0d, h1d);
        p0[d/2]   = __halves2half2(h0a, h0b);
        p0[d/2+1] = __halves2half2(h0c, h0d);
        p1[d/2]   = __halves2half2(h1a, h1b);
        p1[d/2+1] = __halves2half2(h1c, h1d);
    }
}

// ---------------- mean over T per batch ----------------
__global__ void pool_k(const float* __restrict__ xin, float* __restrict__ pooled)
{
    const int b = blockIdx.x;
    const int d = blockIdx.y * 256 + threadIdx.x;
    float s = 0.f;
    for (int t = 0; t < TSEQ; t++)
        s += xin[(size_t)(b*TSEQ + t) * DMODEL + d];
    pooled[b*DMODEL + d] = s * (1.f / (float)TSEQ);
}

// ---------------- head GEMM + bias + L2-normalize ----------------
__global__ void head_k(const float* __restrict__ pooled,
                       const float* __restrict__ hw,
                       const float* __restrict__ hb,
                       float* __restrict__ out)
{
    __shared__ float sp[DMODEL];
    __shared__ float so[EDIM];
    __shared__ float red[32];
    const int b = blockIdx.x;

    for (int d = threadIdx.x; d < DMODEL; d += 256) sp[d] = pooled[b*DMODEL + d];
    __syncthreads();

    float acc[EDIM/256];
    #pragma unroll
    for (int m = 0; m < EDIM/256; m++) acc[m] = hb[threadIdx.x + m*256];
    for (int k = 0; k < DMODEL; k++) {
        const float p = sp[k];
        #pragma unroll
        for (int m = 0; m < EDIM/256; m++)
            acc[m] = fmaf(p, hw[(size_t)k*EDIM + threadIdx.x + m*256], acc[m]);
    }
    #pragma unroll
    for (int m = 0; m < EDIM/256; m++) so[threadIdx.x + m*256] = acc[m];
    __syncthreads();

    float s = 0.f;
    for (int e = threadIdx.x; e < EDIM; e += 256) s = fmaf(so[e], so[e], s);
    const float tot = block_reduce_sum_256(s, red);
    const float inv = 1.f / fmaxf(sqrtf(tot), 1e-12f);
    for (int e = threadIdx.x; e < EDIM; e += 256)
        out[(size_t)b*EDIM + e] = so[e] * inv;
}

// ---------------- host launcher ----------------
extern "C" void kernel_launch(void* const* d_in, const int* in_sizes, int n_in,
                              void* d_out, int out_size)
{
    const float* visual   = (const float*)d_in[0];
    const float* query    = (const float*)d_in[1];
    const float* vis_w    = (const float*)d_in[2];
    const float* vis_b    = (const float*)d_in[3];
    const float* qry_w    = (const float*)d_in[4];
    const float* qry_b    = (const float*)d_in[5];
    const float* norm_ws  = (const float*)d_in[6];
    const float* in_ws    = (const float*)d_in[7];
    const float* dt_bias  = (const float*)d_in[8];
    const float* A_logs   = (const float*)d_in[9];
    const float* D_ssm    = (const float*)d_in[10];
    const float* gnorm_ws = (const float*)d_in[11];
    const float* out_ws   = (const float*)d_in[12];
    const float* norm_f_w = (const float*)d_in[13];
    const float* head_w   = (const float*)d_in[14];
    const float* head_b   = (const float*)d_in[15];
    float* out = (float*)d_out;

    float *hidden, *xin, *proj, *yraw, *pooled;
    __half *ah, *bh;
    cudaGetSymbolAddress((void**)&hidden, g_hidden);
    cudaGetSymbolAddress((void**)&xin,    g_xin);
    cudaGetSymbolAddress((void**)&proj,   g_proj);
    cudaGetSymbolAddress((void**)&yraw,   g_yraw);
    cudaGetSymbolAddress((void**)&pooled, g_pooled);
    cudaGetSymbolAddress((void**)&ah,     g_ah);
    cudaGetSymbolAddress((void**)&bh,     g_bh);

    cudaFuncSetAttribute(hgemm_t<128>, cudaFuncAttributeMaxDynamicSharedMemorySize, GSMEM128);
    cudaFuncSetAttribute(hgemm_t<64>,  cudaFuncAttributeMaxDynamicSharedMemorySize, GSMEM64);

    const dim3 blk(256);

    // ---- initial projections into hidden[b, t, :] ----
    {   // visual: M=1024 → BM=64 grid 8x16
        const size_t S = (size_t)BATCH*TVIS*DMODEL;
        split2_x<<<(unsigned)((S + 255)/256), blk>>>(visual, ah, S);
        tsplit2f<<<dim3(DMODEL/32, DMODEL/64), blk>>>(vis_w, bh, DMODEL, DMODEL);
        hgemm_t<64><<<dim3(DMODEL/128, (BATCH*TVIS)/64), blk, GSMEM64>>>(
            ah, S, bh, (size_t)DMODEL*DMODEL, hidden,
            BATCH*TVIS, DMODEL, DMODEL, vis_b, 0, TVIS, TSEQ, 0);
    }
    {   // query: M=128 → BM=64 grid 8x2
        const size_t S = (size_t)BATCH*TQRY*DMODEL;
        split2_x<<<(unsigned)((S + 255)/256), blk>>>(query, ah, S);
        tsplit2f<<<dim3(DMODEL/32, DMODEL/64), blk>>>(qry_w, bh, DMODEL, DMODEL);
        hgemm_t<64><<<dim3(DMODEL/128, (BATCH*TQRY)/64), blk, GSMEM64>>>(
            ah, S, bh, (size_t)DMODEL*DMODEL, hidden,
            BATCH*TQRY, DMODEL, DMODEL, qry_b, 0, TQRY, TSEQ, TVIS);
    }

    for (int i = 0; i < NLAYERS; i++) {
        const size_t SA = (size_t)ROWS*DMODEL;
        rmsnorm_split_k<<<ROWS, blk>>>(hidden, norm_ws + (size_t)i*DMODEL, ah, SA);

        tsplit2f<<<dim3(PROJ_DIM/32, DMODEL/64), blk>>>(
            in_ws + (size_t)i*DMODEL*PROJ_DIM, bh, DMODEL, PROJ_DIM);
        hgemm_t<128><<<dim3((PROJ_DIM + 127)/128, ROWS/128), blk, GSMEM128>>>(
            ah, SA, bh, (size_t)PROJ_DIM*DMODEL, proj,
            ROWS, PROJ_DIM, DMODEL, nullptr, 0, ROWS, ROWS, 0);

        scan_k<<<BATCH*NHEADS, blk>>>(
            proj, dt_bias + (size_t)i*NHEADS, A_logs + (size_t)i*NHEADS,
            D_ssm + (size_t)i*NHEADS, yraw);

        const size_t SG = (size_t)ROWS*DINNER;
        gate_gnorm_split_k<<<ROWS, blk>>>(proj, yraw, gnorm_ws + (size_t)i*DINNER, ah, SG);

        tsplit2f<<<dim3(DMODEL/32, DINNER/64), blk>>>(
            out_ws + (size_t)i*DINNER*DMODEL, bh, DINNER, DMODEL);
        hgemm_t<64><<<dim3(DMODEL/128, ROWS/64), blk, GSMEM64>>>(
            ah, SG, bh, (size_t)DMODEL*DINNER, hidden,
            ROWS, DMODEL, DINNER, nullptr, 1, ROWS, ROWS, 0);
    }

    rmsnorm_k<<<ROWS, blk>>>(hidden, norm_f_w, xin, DMODEL);
    pool_k<<<dim3(BATCH, DMODEL/256), blk>>>(xin, pooled);
    head_k<<<BATCH, blk>>>(pooled, head_w, head_b, out);
}

// round 7
// speedup vs baseline: 2.7972x; 1.0565x over previous
#include <cuda_runtime.h>
#include <cuda_fp16.h>
#include <math.h>
#include <stdint.h>

// ---------------- problem constants ----------------
#define BATCH   4
#define TSEQ    288
#define TVIS    256
#define TQRY    32
#define DMODEL  1024
#define DINNER  2048
#define NHEADS  32
#define NSTATE  128
#define PDIM    64
#define NLAYERS 12
#define PROJ_DIM 4384
#define EDIM    1536
#define ROWS    (BATCH*TSEQ)    // 1152
#define ALPHA_C 0.5f

// ---------------- scratch (device globals; no allocation) ----------------
__device__ float g_hidden[ROWS*DMODEL];
__device__ float g_xin   [ROWS*DMODEL];
__device__ float g_proj  [ROWS*PROJ_DIM];
__device__ float g_yraw  [ROWS*DINNER];
__device__ float g_pooled[BATCH*DMODEL];
__device__ __align__(16) __half g_ah[2ull*1152*2048];
__device__ __align__(16) __half g_bh[2ull*4384*1024];

// ---------------- helpers ----------------
__device__ __forceinline__ float block_reduce_sum_256(float v, float* red)
{
    #pragma unroll
    for (int o = 16; o; o >>= 1) v += __shfl_xor_sync(0xffffffffu, v, o);
    const int warp = threadIdx.x >> 5, lane = threadIdx.x & 31;
    if (lane == 0) red[warp] = v;
    __syncthreads();
    if (threadIdx.x < 32) {
        float t = (threadIdx.x < 8) ? red[threadIdx.x] : 0.f;
        #pragma unroll
        for (int o = 4; o; o >>= 1) t += __shfl_xor_sync(0xffffffffu, t, o);
        if (threadIdx.x == 0) red[0] = t;
    }
    __syncthreads();
    return red[0];
}

__device__ __forceinline__ void split2(float x, __half& h0, __half& h1)
{
    h0 = __float2half_rn(x);
    h1 = __float2half_rn(x - __half2float(h0));
}

#define MMA16(cc, aa, bb)                                                        \
  asm volatile("mma.sync.aligned.m16n8k16.row.col.f32.f16.f16.f32 "             \
    "{%0,%1,%2,%3}, {%4,%5,%6,%7}, {%8,%9}, {%0,%1,%2,%3};\n"                    \
    : "+f"((cc)[0]), "+f"((cc)[1]), "+f"((cc)[2]), "+f"((cc)[3])                 \
    : "r"((aa)[0]), "r"((aa)[1]), "r"((aa)[2]), "r"((aa)[3]),                    \
      "r"((bb)[0]), "r"((bb)[1]))

__device__ __forceinline__ void ldsm4(uint32_t* r, uint32_t addr)
{
    asm volatile("ldmatrix.sync.aligned.m8n8.x4.shared.b16 {%0,%1,%2,%3}, [%4];"
                 : "=r"(r[0]), "=r"(r[1]), "=r"(r[2]), "=r"(r[3]) : "r"(addr));
}
__device__ __forceinline__ void ldsm2(uint32_t* r, uint32_t addr)
{
    asm volatile("ldmatrix.sync.aligned.m8n8.x2.shared.b16 {%0,%1}, [%2];"
                 : "=r"(r[0]), "=r"(r[1]) : "r"(addr));
}

__device__ __forceinline__ void cpasync16(uint32_t dst, const void* src, int sz)
{
    asm volatile("cp.async.cg.shared.global [%0], [%1], 16, %2;\n"
                 :: "r"(dst), "l"(src), "r"(sz));
}
__device__ __forceinline__ void cpasync4(uint32_t dst, const void* src)
{
    asm volatile("cp.async.ca.shared.global [%0], [%1], 4;\n"
                 :: "r"(dst), "l"(src));
}

// ---------------- prep: split fp32 -> 2 fp16 planes (inputs only) ----------------
__global__ void split2_x(const float* __restrict__ x, __half* __restrict__ out, size_t S)
{
    size_t i = (size_t)blockIdx.x * blockDim.x + threadIdx.x;
    if (i < S) {
        __half h0, h1; split2(x[i], h0, h1);
        out[i] = h0; out[S + i] = h1;
    }
}

// ---------------- prep: transpose KxN fp32 -> 2 planes [N][K] fp16 ----------------
__global__ void tsplit2f(const float* __restrict__ W, __half* __restrict__ out,
                         int K, int N)
{
    __shared__ float tile[64][33];
    const int n0 = blockIdx.x * 32, k0 = blockIdx.y * 64;
    const int tid = threadIdx.x;
    const int r = tid >> 5, c = tid & 31;
    #pragma unroll
    for (int i = 0; i < 8; i++)
        tile[i*8 + r][c] = W[(size_t)(k0 + i*8 + r) * N + n0 + c];
    __syncthreads();

    const size_t NK = (size_t)N * K;
    const int ns = tid >> 5;
    const int kp = tid & 31;
    #pragma unroll
    for (int j = 0; j < 4; j++) {
        const int nl = j*8 + ns;
        const int n  = n0 + nl;
        const float f0 = tile[2*kp    ][nl];
        const float f1 = tile[2*kp + 1][nl];
        __half a0, a1, b0, b1;
        split2(f0, a0, a1);
        split2(f1, b0, b1);
        __half2* p0 = (__half2*)(out + (size_t)n * K + k0);
        __half2* p1 = (__half2*)(out + NK + (size_t)n * K + k0);
        p0[kp] = __halves2half2(a0, b0);
        p1[kp] = __halves2half2(a1, b1);
    }
}

// ---------------- fp16x2 mma.sync GEMM, BM=64, 2 CTAs/SM ----------------
// C[map(r)] (+)= A[r] @ B^T + bias.  A planes [M][K], B planes [N][K].
// M % 64 == 0, K % 64 == 0, N guarded.
#define BPLANE 16384
#define APLANE 8192                       // 64 rows x 128 B
#define STAGE  (2*APLANE + 2*BPLANE)      // 48 KB
#define GSMEM  (2*STAGE)                  // 96 KB
__global__ __launch_bounds__(256, 2)
void hgemm_k(const __half* __restrict__ Ah, size_t aplane,
             const __half* __restrict__ Bh, size_t bplane,
             float* __restrict__ C, int M, int N, int K,
             const float* __restrict__ bias, int accum,
             int Tin, int Tout, int toff)
{
    extern __shared__ char sm[];
    const uint32_t smb = (uint32_t)__cvta_generic_to_shared(sm);

    const int tid  = threadIdx.x;
    const int warp = tid >> 5, lane = tid & 31;
    const int gid  = lane >> 2, tg = lane & 3;
    const int row0 = blockIdx.y * 64;
    const int col0 = blockIdx.x * 128;
    const int m_off = (warp & 1) * 32;
    const int n_off = (warp >> 1) * 32;

    float c[2][4][4];
    #pragma unroll
    for (int mi = 0; mi < 2; mi++)
        #pragma unroll
        for (int ni = 0; ni < 4; ni++)
            #pragma unroll
            for (int q = 0; q < 4; q++) c[mi][ni][q] = 0.f;

    // ---- global->smem load mapping ----
    const int larow  = tid >> 2;          // 0..63 A row
    const int cbase  = (tid & 3) * 2;     // 2 chunks per thread
    const int lbrow  = tid >> 1;          // 0..127 B row
    const int cbaseB = (tid & 1) * 4;     // 4 chunks per thread
    const int brow   = col0 + lbrow;
    const int bval   = (brow < N) ? 16 : 0;
    const __half* Asrc0 = Ah + (size_t)(row0 + larow) * K;
    const __half* Asrc1 = Asrc0 + aplane;
    const __half* Bsrc0 = Bh + (size_t)((brow < N) ? brow : 0) * K;
    const __half* Bsrc1 = Bsrc0 + bplane;

    // ---- ldmatrix per-lane address invariants ----
    const int la   = lane & 15;
    const int asel = lane >> 4;
    const int lb   = lane & 7;
    const int bsel = (lane >> 3) & 1;
    uint32_t aoff[2]; int ar7[2];
    #pragma unroll
    for (int mi = 0; mi < 2; mi++) {
        const int r = m_off + mi*16 + la;
        aoff[mi] = (uint32_t)r * 128;
        ar7[mi]  = r & 7;
    }
    uint32_t boff[4]; int br7[4];
    #pragma unroll
    for (int ni = 0; ni < 4; ni++) {
        const int r = n_off + ni*8 + lb;
        boff[ni] = (uint32_t)r * 128;
        br7[ni]  = r & 7;
    }

    const int nc = K >> 6;

    // ---- prologue ----
    {
        const uint32_t sb = smb;
        #pragma unroll
        for (int j = 0; j < 2; j++) {
            const int ch = cbase + j;
            const uint32_t sw = (uint32_t)((ch ^ (larow & 7)) << 4);
            cpasync16(sb + larow*128 + sw,          Asrc0 + ch*8, 16);
            cpasync16(sb + APLANE + larow*128 + sw, Asrc1 + ch*8, 16);
        }
        #pragma unroll
        for (int j = 0; j < 4; j++) {
            const int ch = cbaseB + j;
            const uint32_t sw = (uint32_t)((ch ^ (lbrow & 7)) << 4);
            cpasync16(sb + 2*APLANE + lbrow*128 + sw,          Bsrc0 + ch*8, bval);
            cpasync16(sb + 2*APLANE + BPLANE + lbrow*128 + sw, Bsrc1 + ch*8, bval);
        }
        asm volatile("cp.async.commit_group;\n");
    }

    for (int kc = 0; kc < nc; kc++) {
        if (kc + 1 < nc) {
            const int k0 = (kc + 1) << 6;
            const uint32_t sb = smb + ((kc + 1) & 1) * STAGE;
            #pragma unroll
            for (int j = 0; j < 2; j++) {
                const int ch = cbase + j;
                const uint32_t sw = (uint32_t)((ch ^ (larow & 7)) << 4);
                cpasync16(sb + larow*128 + sw,          Asrc0 + k0 + ch*8, 16);
                cpasync16(sb + APLANE + larow*128 + sw, Asrc1 + k0 + ch*8, 16);
            }
            #pragma unroll
            for (int j = 0; j < 4; j++) {
                const int ch = cbaseB + j;
                const uint32_t sw = (uint32_t)((ch ^ (lbrow & 7)) << 4);
                cpasync16(sb + 2*APLANE + lbrow*128 + sw,          Bsrc0 + k0 + ch*8, bval);
                cpasync16(sb + 2*APLANE + BPLANE + lbrow*128 + sw, Bsrc1 + k0 + ch*8, bval);
            }
        }
        asm volatile("cp.async.commit_group;\n");
        asm volatile("cp.async.wait_group 1;\n");
        __syncthreads();

        const uint32_t S0 = smb + (kc & 1) * STAGE;
        const uint32_t S1 = S0 + APLANE;
        const uint32_t S2 = S0 + 2*APLANE;
        const uint32_t S3 = S2 + BPLANE;

        #pragma unroll
        for (int s = 0; s < 4; s++) {
            uint32_t b0[4][2], b1[4][2];
            #pragma unroll
            for (int ni = 0; ni < 4; ni++) {
                const uint32_t swb = (uint32_t)(((2*s + bsel) ^ br7[ni]) << 4);
                ldsm2(b0[ni], S2 + boff[ni] + swb);
                ldsm2(b1[ni], S3 + boff[ni] + swb);
            }
            #pragma unroll
            for (int mi = 0; mi < 2; mi++) {
                const uint32_t swa = (uint32_t)(((2*s + asel) ^ ar7[mi]) << 4);
                uint32_t a0[4], a1[4];
                ldsm4(a0, S0 + aoff[mi] + swa);
                ldsm4(a1, S1 + aoff[mi] + swa);
                #pragma unroll
                for (int ni = 0; ni < 4; ni++) {
                    MMA16(c[mi][ni], a0, b0[ni]);
                    MMA16(c[mi][ni], a0, b1[ni]);
                    MMA16(c[mi][ni], a1, b0[ni]);
                }
            }
        }
        __syncthreads();
    }

    // ---- epilogue ----
    #pragma unroll
    for (int mi = 0; mi < 2; mi++) {
        #pragma unroll
        for (int half = 0; half < 2; half++) {
            const int r = row0 + m_off + mi*16 + gid + half*8;
            const int orow = (r / Tin) * Tout + toff + (r % Tin);
            #pragma unroll
            for (int ni = 0; ni < 4; ni++) {
                const int col = col0 + n_off + ni*8 + tg*2;
                if (col < N) {
                    float v0 = c[mi][ni][half*2 + 0];
                    float v1 = c[mi][ni][half*2 + 1];
                    if (bias) { v0 += bias[col]; v1 += bias[col+1]; }
                    float* dst = C + (size_t)orow * N + col;
                    if (accum) { v0 += dst[0]; v1 += dst[1]; }
                    *reinterpret_cast<float2*>(dst) = make_float2(v0, v1);
                }
            }
        }
    }
}

// ---------------- RMSNorm (fp32 out, final layer) ----------------
__global__ void rmsnorm_k(const float* __restrict__ x, const float* __restrict__ w,
                          float* __restrict__ out, int D)
{
    __shared__ float red[32];
    const int r = blockIdx.x;
    const float* xr = x + (size_t)r * D;
    float s = 0.f;
    for (int d = threadIdx.x; d < D; d += 256) { float v = xr[d]; s = fmaf(v, v, s); }
    const float tot = block_reduce_sum_256(s, red);
    const float rms = rsqrtf(tot / (float)D + 1e-5f);
    for (int d = threadIdx.x; d < D; d += 256)
        out[(size_t)r * D + d] = xr[d] * rms * w[d];
}

// ---------------- RMSNorm fused with fp16x2 split (D = 1024) ----------------
__global__ void rmsnorm_split_k(const float* __restrict__ x, const float* __restrict__ w,
                                __half* __restrict__ out, size_t S)
{
    __shared__ float red[32];
    const int r = blockIdx.x;
    const int tid = threadIdx.x;
    const float4 xv = *(const float4*)(x + (size_t)r * DMODEL + tid*4);
    const float4 wv = *(const float4*)(w + tid*4);
    float s = xv.x*xv.x + xv.y*xv.y + xv.z*xv.z + xv.w*xv.w;
    const float tot = block_reduce_sum_256(s, red);
    const float rms = rsqrtf(tot / (float)DMODEL + 1e-5f);
    float v0 = xv.x*rms*wv.x, v1 = xv.y*rms*wv.y, v2 = xv.z*rms*wv.z, v3 = xv.w*rms*wv.w;
    __half h0a, h1a, h0b, h1b, h0c, h1c, h0d, h1d;
    split2(v0, h0a, h1a); split2(v1, h0b, h1b);
    split2(v2, h0c, h1c); split2(v3, h0d, h1d);
    __half2* p0 = (__half2*)(out + (size_t)r * DMODEL);
    __half2* p1 = (__half2*)(out + S + (size_t)r * DMODEL);
    p0[tid*2]   = __halves2half2(h0a, h0b);
    p0[tid*2+1] = __halves2half2(h0c, h0d);
    p1[tid*2]   = __halves2half2(h1a, h1b);
    p1[tid*2+1] = __halves2half2(h1c, h1d);
}

// ---------------- SSD scan: 3-deep cp.async pipeline ----------------
#define SCX  0
#define SCB  64
#define SCC  192
#define SCDT 320
__global__ void scan_k(const float* __restrict__ proj,
                       const float* __restrict__ dt_bias,
                       const float* __restrict__ A_log,
                       const float* __restrict__ Dssm,
                       float* __restrict__ yraw)
{
    const int b    = blockIdx.x >> 5;
    const int h    = blockIdx.x & 31;
    const int tid  = threadIdx.x;
    const int warp = tid >> 5, lane = tid & 31;

    __shared__ float st[3][324];

    const float dtb  = dt_bias[h];
    const float Aval = -expf(A_log[h]);
    const float Dval = Dssm[h];

    float hs[8][4];
    #pragma unroll
    for (int i = 0; i < 8; i++)
        #pragma unroll
        for (int j = 0; j < 4; j++) hs[i][j] = 0.f;

    float xprev[8];
    float bprev[4];
    float dtprev = 0.f;
    #pragma unroll
    for (int i = 0; i < 8; i++) xprev[i] = 0.f;
    #pragma unroll
    for (int j = 0; j < 4; j++) bprev[j] = 0.f;

    const int pbase = warp * 8;
    const int nbase = lane * 4;

    uint32_t stb[3];
    stb[0] = (uint32_t)__cvta_generic_to_shared(&st[0][0]);
    stb[1] = (uint32_t)__cvta_generic_to_shared(&st[1][0]);
    stb[2] = (uint32_t)__cvta_generic_to_shared(&st[2][0]);

    auto issue = [&](int buf, int t) {
        const float* pr = proj + (size_t)(b * TSEQ + t) * PROJ_DIM;
        const uint32_t base = stb[buf];
        if (tid < 16)
            cpasync16(base + (SCX + tid*4)*4,  pr + DINNER + h*PDIM + tid*4, 16);
        else if (tid < 48)
            cpasync16(base + (SCB + (tid-16)*4)*4, pr + 2*DINNER + (tid-16)*4, 16);
        else if (tid < 80)
            cpasync16(base + (SCC + (tid-48)*4)*4, pr + 2*DINNER + NSTATE + (tid-48)*4, 16);
        else if (tid == 80)
            cpasync4(base + SCDT*4, pr + 2*DINNER + 2*NSTATE + h);
        asm volatile("cp.async.commit_group;\n");
    };

    issue(0, 0);
    issue(1, 1);

    int buf = 0;
    for (int t = 0; t < TSEQ; t++) {
        asm volatile("cp.async.wait_group 1;\n");
        __syncthreads();
        if (t + 2 < TSEQ) {
            int nb = buf + 2; if (nb >= 3) nb -= 3;
            issue(nb, t + 2);
        } else {
            asm volatile("cp.async.commit_group;\n");
        }

        const float* sb = st[buf];
        const float vdt = sb[SCDT] + dtb;
        const float dt  = (vdt > 20.f) ? vdt : log1pf(expf(vdt));
        const float da  = expf(dt * Aval);
        const float cu  = (1.f - ALPHA_C) * dt;
        const float cup = da * ALPHA_C * dtprev;

        float bc[4], cc[4];
        #pragma unroll
        for (int j = 0; j < 4; j++) { bc[j] = sb[SCB + nbase + j]; cc[j] = sb[SCC + nbase + j]; }

        const int row = b * TSEQ + t;
        #pragma unroll
        for (int i = 0; i < 8; i++) {
            const float xr  = sb[SCX + pbase + i];
            const float xpi = cup * xprev[i];
            const float xci = cu  * xr;
            float yp = 0.f;
            #pragma unroll
            for (int j = 0; j < 4; j++) {
                const float u = fmaf(xpi, bprev[j], xci * bc[j]);
                hs[i][j] = fmaf(da, hs[i][j], u);
                yp = fmaf(hs[i][j], cc[j], yp);
            }
            #pragma unroll
            for (int o = 16; o; o >>= 1) yp += __shfl_xor_sync(0xffffffffu, yp, o);
            if (lane == 0)
                yraw[(size_t)row * DINNER + h*PDIM + pbase + i] = fmaf(Dval, xr, yp);
            xprev[i] = xr;
        }
        #pragma unroll
        for (int j = 0; j < 4; j++) bprev[j] = bc[j];
        dtprev = dt;
        buf++; if (buf >= 3) buf = 0;
    }
}

// ---------------- gate + gnorm fused with fp16x2 split (D = 2048) ----------------
__global__ void gate_gnorm_split_k(const float* __restrict__ proj,
                                   const float* __restrict__ yraw,
                                   const float* __restrict__ gw,
                                   __half* __restrict__ out, size_t S)
{
    __shared__ float red[32];
    __shared__ float gbuf[DINNER];
    const int r = blockIdx.x;
    const int tid = threadIdx.x;
    const float* pz = proj + (size_t)r * PROJ_DIM;
    const float* yr = yraw + (size_t)r * DINNER;

    float s = 0.f;
    #pragma unroll
    for (int it = 0; it < 2; it++) {
        const int d = (tid + it*256) * 4;
        const float4 zv = *(const float4*)(pz + d);
        const float4 yv = *(const float4*)(yr + d);
        float g0 = yv.x * zv.x / (1.f + expf(-zv.x));
        float g1 = yv.y * zv.y / (1.f + expf(-zv.y));
        float g2 = yv.z * zv.z / (1.f + expf(-zv.z));
        float g3 = yv.w * zv.w / (1.f + expf(-zv.w));
        gbuf[d+0] = g0; gbuf[d+1] = g1; gbuf[d+2] = g2; gbuf[d+3] = g3;
        s += g0*g0 + g1*g1 + g2*g2 + g3*g3;
    }
    const float tot = block_reduce_sum_256(s, red);
    const float rms = rsqrtf(tot / (float)DINNER + 1e-5f);

    __half2* p0 = (__half2*)(out + (size_t)r * DINNER);
    __half2* p1 = (__half2*)(out + S + (size_t)r * DINNER);
    #pragma unroll
    for (int it = 0; it < 2; it++) {
        const int d = (tid + it*256) * 4;
        const float4 wv = *(const float4*)(gw + d);
        float v0 = gbuf[d+0]*rms*wv.x, v1 = gbuf[d+1]*rms*wv.y;
        float v2 = gbuf[d+2]*rms*wv.z, v3 = gbuf[d+3]*rms*wv.w;
        __half h0a, h1a, h0b, h1b, h0c, h1c, h0d, h1d;
        split2(v0, h0a, h1a); split2(v1, h0b, h1b);
        split2(v2, h0c, h1c); split2(v3, h0d, h1d);
        p0[d/2]   = __halves2half2(h0a, h0b);
        p0[d/2+1] = __halves2half2(h0c, h0d);
        p1[d/2]   = __halves2half2(h1a, h1b);
        p1[d/2+1] = __halves2half2(h1c, h1d);
    }
}

// ---------------- mean over T per batch ----------------
__global__ void pool_k(const float* __restrict__ xin, float* __restrict__ pooled)
{
    const int b = blockIdx.x;
    const int d = blockIdx.y * 256 + threadIdx.x;
    float s = 0.f;
    for (int t = 0; t < TSEQ; t++)
        s += xin[(size_t)(b*TSEQ + t) * DMODEL + d];
    pooled[b*DMODEL + d] = s * (1.f / (float)TSEQ);
}

// ---------------- head GEMM + bias + L2-normalize ----------------
__global__ void head_k(const float* __restrict__ pooled,
                       const float* __restrict__ hw,
                       const float* __restrict__ hb,
                       float* __restrict__ out)
{
    __shared__ float sp[DMODEL];
    __shared__ float so[EDIM];
    __shared__ float red[32];
    const int b = blockIdx.x;

    for (int d = threadIdx.x; d < DMODEL; d += 256) sp[d] = pooled[b*DMODEL + d];
    __syncthreads();

    float acc[EDIM/256];
    #pragma unroll
    for (int m = 0; m < EDIM/256; m++) acc[m] = hb[threadIdx.x + m*256];
    for (int k = 0; k < DMODEL; k++) {
        const float p = sp[k];
        #pragma unroll
        for (int m = 0; m < EDIM/256; m++)
            acc[m] = fmaf(p, hw[(size_t)k*EDIM + threadIdx.x + m*256], acc[m]);
    }
    #pragma unroll
    for (int m = 0; m < EDIM/256; m++) so[threadIdx.x + m*256] = acc[m];
    __syncthreads();

    float s = 0.f;
    for (int e = threadIdx.x; e < EDIM; e += 256) s = fmaf(so[e], so[e], s);
    const float tot = block_reduce_sum_256(s, red);
    const float inv = 1.f / fmaxf(sqrtf(tot), 1e-12f);
    for (int e = threadIdx.x; e < EDIM; e += 256)
        out[(size_t)b*EDIM + e] = so[e] * inv;
}

// ---------------- host launcher ----------------
extern "C" void kernel_launch(void* const* d_in, const int* in_sizes, int n_in,
                              void* d_out, int out_size)
{
    const float* visual   = (const float*)d_in[0];
    const float* query    = (const float*)d_in[1];
    const float* vis_w    = (const float*)d_in[2];
    const float* vis_b    = (const float*)d_in[3];
    const float* qry_w    = (const float*)d_in[4];
    const float* qry_b    = (const float*)d_in[5];
    const float* norm_ws  = (const float*)d_in[6];
    const float* in_ws    = (const float*)d_in[7];
    const float* dt_bias  = (const float*)d_in[8];
    const float* A_logs   = (const float*)d_in[9];
    const float* D_ssm    = (const float*)d_in[10];
    const float* gnorm_ws = (const float*)d_in[11];
    const float* out_ws   = (const float*)d_in[12];
    const float* norm_f_w = (const float*)d_in[13];
    const float* head_w   = (const float*)d_in[14];
    const float* head_b   = (const float*)d_in[15];
    float* out = (float*)d_out;

    float *hidden, *xin, *proj, *yraw, *pooled;
    __half *ah, *bh;
    cudaGetSymbolAddress((void**)&hidden, g_hidden);
    cudaGetSymbolAddress((void**)&xin,    g_xin);
    cudaGetSymbolAddress((void**)&proj,   g_proj);
    cudaGetSymbolAddress((void**)&yraw,   g_yraw);
    cudaGetSymbolAddress((void**)&pooled, g_pooled);
    cudaGetSymbolAddress((void**)&ah,     g_ah);
    cudaGetSymbolAddress((void**)&bh,     g_bh);

    cudaFuncSetAttribute(hgemm_k, cudaFuncAttributeMaxDynamicSharedMemorySize, GSMEM);

    const dim3 blk(256);

    // ---- initial projections into hidden[b, t, :] ----
    {   // visual: M=1024
        const size_t S = (size_t)BATCH*TVIS*DMODEL;
        split2_x<<<(unsigned)((S + 255)/256), blk>>>(visual, ah, S);
        tsplit2f<<<dim3(DMODEL/32, DMODEL/64), blk>>>(vis_w, bh, DMODEL, DMODEL);
        hgemm_k<<<dim3(DMODEL/128, (BATCH*TVIS)/64), blk, GSMEM>>>(
            ah, S, bh, (size_t)DMODEL*DMODEL, hidden,
            BATCH*TVIS, DMODEL, DMODEL, vis_b, 0, TVIS, TSEQ, 0);
    }
    {   // query: M=128
        const size_t S = (size_t)BATCH*TQRY*DMODEL;
        split2_x<<<(unsigned)((S + 255)/256), blk>>>(query, ah, S);
        tsplit2f<<<dim3(DMODEL/32, DMODEL/64), blk>>>(qry_w, bh, DMODEL, DMODEL);
        hgemm_k<<<dim3(DMODEL/128, (BATCH*TQRY)/64), blk, GSMEM>>>(
            ah, S, bh, (size_t)DMODEL*DMODEL, hidden,
            BATCH*TQRY, DMODEL, DMODEL, qry_b, 0, TQRY, TSEQ, TVIS);
    }

    for (int i = 0; i < NLAYERS; i++) {
        const size_t SA = (size_t)ROWS*DMODEL;
        rmsnorm_split_k<<<ROWS, blk>>>(hidden, norm_ws + (size_t)i*DMODEL, ah, SA);

        tsplit2f<<<dim3(PROJ_DIM/32, DMODEL/64), blk>>>(
            in_ws + (size_t)i*DMODEL*PROJ_DIM, bh, DMODEL, PROJ_DIM);
        hgemm_k<<<dim3((PROJ_DIM + 127)/128, ROWS/64), blk, GSMEM>>>(
            ah, SA, bh, (size_t)PROJ_DIM*DMODEL, proj,
            ROWS, PROJ_DIM, DMODEL, nullptr, 0, ROWS, ROWS, 0);

        scan_k<<<BATCH*NHEADS, blk>>>(
            proj, dt_bias + (size_t)i*NHEADS, A_logs + (size_t)i*NHEADS,
            D_ssm + (size_t)i*NHEADS, yraw);

        const size_t SG = (size_t)ROWS*DINNER;
        gate_gnorm_split_k<<<ROWS, blk>>>(proj, yraw, gnorm_ws + (size_t)i*DINNER, ah, SG);

        tsplit2f<<<dim3(DMODEL/32, DINNER/64), blk>>>(
            out_ws + (size_t)i*DINNER*DMODEL, bh, DINNER, DMODEL);
        hgemm_k<<<dim3(DMODEL/128, ROWS/64), blk, GSMEM>>>(
            ah, SG, bh, (size_t)DMODEL*DINNER, hidden,
            ROWS, DMODEL, DINNER, nullptr, 1, ROWS, ROWS, 0);
    }

    rmsnorm_k<<<ROWS, blk>>>(hidden, norm_f_w, xin, DMODEL);
    pool_k<<<dim3(BATCH, DMODEL/256), blk>>>(xin, pooled);
    head_k<<<BATCH, blk>>>(pooled, head_w, head_b, out);
}